// round 13
// baseline (speedup 1.0000x reference)
#include <cuda_runtime.h>
#include <cuda_fp16.h>
#include <mma.h>
#include <cstddef>

using namespace nvcuda;

#define Bc 4
#define Sc 1024
#define Dc 1024
#define Hc 16
#define DKc 64
#define DVc 64
#define Mc (Bc * Sc)
#define HDc (Hc * DKc)
#define QP_ELEMS (Mc * HDc)

// ---------------- Static device scratch (fp16) ----------------
__device__ __half g_Qp[QP_ELEMS];                    // [B,H,S,64]
__device__ __half g_Kp[QP_ELEMS];
__device__ __half g_Vp[QP_ELEMS];
__device__ __half g_ctx[Mc * HDc];                   // [B,S,1024]
__device__ __half g_attn_h[(size_t)Bc * Hc * Sc * Sc]; // fp16 probs
__device__ float g_obuf[Mc * Dc];
__device__ float g_attn_fb[(size_t)Bc * Hc * Sc * Sc];
__device__ int   g_mask_mode;

using hfrag_a  = wmma::fragment<wmma::matrix_a, 16, 16, 16, __half, wmma::row_major>;
using hfrag_b  = wmma::fragment<wmma::matrix_b, 16, 16, 16, __half, wmma::row_major>;
using hfrag_bc = wmma::fragment<wmma::matrix_b, 16, 16, 16, __half, wmma::col_major>;
using hfrag_c  = wmma::fragment<wmma::accumulator, 16, 16, 16, float>;

__device__ __forceinline__ void cvt_store4_h(__half* d, float4 v) {
    d[0] = __float2half(v.x);
    d[1] = __float2half(v.y);
    d[2] = __float2half(v.z);
    d[3] = __float2half(v.w);
}

// ---------------------------------------------------------------------------
__global__ void detect_mask_kernel(const unsigned int* __restrict__ m) {
    bool allint = true, allfloat = true;
    for (int i = 0; i < 1024; i++) {
        unsigned int w = m[i];
        if (w > 1u) allint = false;
        if (w != 0u && w != 0x3F800000u) allfloat = false;
    }
    g_mask_mode = allint ? 0 : (allfloat ? 2 : 1);
}

// ---------------------------------------------------------------------------
// Merged QKV projection (uniform single-fp16): grid z = 0(Q), 1(K), 2(V).
// BM=128, BN=128, BK=16, warp tile 32x64 (2x4), double-buffered smem.
// ---------------------------------------------------------------------------
__global__ __launch_bounds__(256)
void qkv_proj(const float* __restrict__ q, const float* __restrict__ k,
              const float* __restrict__ v,
              const float* __restrict__ Wq, const float* __restrict__ Wk,
              const float* __restrict__ Wv,
              const float* __restrict__ bq, const float* __restrict__ bk,
              const float* __restrict__ bv,
              __half* __restrict__ Qp, __half* __restrict__ Kp,
              __half* __restrict__ Vp) {
    constexpr int LDA = 24;
    constexpr int LDW = 136;
    constexpr int LDST = 132;

    __shared__ __align__(16) char buf[33792];
    __half* As = (__half*)buf;          // [2][128][24]
    __half* Ws = As + 2 * 128 * LDA;    // [2][16][136]
    float* stg = (float*)buf;           // [64][132] epilogue reuse

    const int z = blockIdx.z;
    const float* A    = (z == 0) ? q  : (z == 1) ? k  : v;
    const float* W    = (z == 0) ? Wq : (z == 1) ? Wk : Wv;
    const float* bias = (z == 0) ? bq : (z == 1) ? bk : bv;
    __half* C         = (z == 0) ? Qp : (z == 1) ? Kp : Vp;

    const int tid = threadIdx.x;
    const int w = tid >> 5;
    const int wm = w >> 1;
    const int wn = w & 1;
    const int row0 = blockIdx.y * 128;
    const int col0 = blockIdx.x * 128;

    const int ar = tid >> 2, ac = (tid & 3) * 4;
    const int wr0 = tid >> 5, wc0 = (tid & 31) * 4;

    hfrag_c acc[2][4];
#pragma unroll
    for (int ti = 0; ti < 2; ti++)
#pragma unroll
        for (int tj = 0; tj < 4; tj++) wmma::fill_fragment(acc[ti][tj], 0.0f);

    float4 ra0, ra1, rw0, rw1;
    ra0 = *(const float4*)&A[(size_t)(row0 + ar) * Dc + ac];
    ra1 = *(const float4*)&A[(size_t)(row0 + ar + 64) * Dc + ac];
    rw0 = *(const float4*)&W[(size_t)wr0 * HDc + col0 + wc0];
    rw1 = *(const float4*)&W[(size_t)(wr0 + 8) * HDc + col0 + wc0];
    cvt_store4_h(As + ar * LDA + ac, ra0);
    cvt_store4_h(As + (ar + 64) * LDA + ac, ra1);
    cvt_store4_h(Ws + wr0 * LDW + wc0, rw0);
    cvt_store4_h(Ws + (wr0 + 8) * LDW + wc0, rw1);
    __syncthreads();

    for (int kt = 0; kt < 64; kt++) {
        if (kt < 63) {
            int kk = (kt + 1) * 16;
            ra0 = *(const float4*)&A[(size_t)(row0 + ar) * Dc + kk + ac];
            ra1 = *(const float4*)&A[(size_t)(row0 + ar + 64) * Dc + kk + ac];
            rw0 = *(const float4*)&W[(size_t)(kk + wr0) * HDc + col0 + wc0];
            rw1 = *(const float4*)&W[(size_t)(kk + wr0 + 8) * HDc + col0 + wc0];
        }
        const int cur = kt & 1;
        const int cb = cur * 128 * LDA;
        const int wb = cur * 16 * LDW;

        hfrag_a fa[2];
#pragma unroll
        for (int ti = 0; ti < 2; ti++)
            wmma::load_matrix_sync(fa[ti], As + cb + (wm * 32 + ti * 16) * LDA, LDA);
#pragma unroll
        for (int tj = 0; tj < 4; tj++) {
            hfrag_b fb;
            wmma::load_matrix_sync(fb, Ws + wb + wn * 64 + tj * 16, LDW);
#pragma unroll
            for (int ti = 0; ti < 2; ti++)
                wmma::mma_sync(acc[ti][tj], fa[ti], fb, acc[ti][tj]);
        }

        if (kt < 63) {
            const int nb = (cur ^ 1) * 128 * LDA;
            const int nw = (cur ^ 1) * 16 * LDW;
            cvt_store4_h(As + nb + ar * LDA + ac, ra0);
            cvt_store4_h(As + nb + (ar + 64) * LDA + ac, ra1);
            cvt_store4_h(Ws + nw + wr0 * LDW + wc0, rw0);
            cvt_store4_h(Ws + (wr0 + 8) * LDW + nw + wc0, rw1);
        }
        __syncthreads();
    }

#pragma unroll
    for (int ph = 0; ph < 2; ph++) {
        if ((wm >> 1) == ph) {
#pragma unroll
            for (int ti = 0; ti < 2; ti++)
#pragma unroll
                for (int tj = 0; tj < 4; tj++)
                    wmma::store_matrix_sync(&stg[((wm & 1) * 32 + ti * 16) * LDST + wn * 64 + tj * 16],
                                            acc[ti][tj], LDST, wmma::mem_row_major);
        }
        __syncthreads();
#pragma unroll
        for (int i = tid; i < 2048; i += 256) {
            int r = i >> 5, c4 = (i & 31) * 4;
            int m = row0 + ph * 64 + r;
            int col = col0 + c4;
            float4 vv = *(float4*)&stg[r * LDST + c4];
            float4 bi = *(const float4*)&bias[col];
            vv.x += bi.x; vv.y += bi.y; vv.z += bi.z; vv.w += bi.w;
            int b = m >> 10, s = m & 1023, h = col >> 6, d = col & 63;
            cvt_store4_h(C + (((size_t)b * Hc + h) * Sc + s) * 64 + d, vv);
        }
        __syncthreads();
    }
}

// ---------------------------------------------------------------------------
// Fused scores + mask + softmax (fp16-single).
// Block = 16 q-rows of one (b,h) x full K=1024. 8 warps; warp owns a 16-col
// strip of each 128-col K tile. Q frags hoisted; K double-buffered via
// register prefetch. smem 105KB -> 2 CTAs/SM.
// Writes fp32 probs (output) + fp16 probs (for context) ONCE; raw scores
// never touch DRAM.
// ---------------------------------------------------------------------------
#define LDS_F 1032
#define LDK_F 72
#define FUSED_SMEM (16 * LDS_F * 4 + 16 * LDK_F * 2 + 2 * 128 * LDK_F * 2)

__global__ __launch_bounds__(256, 2)
void fused_scores_softmax(const __half* __restrict__ Qp, const __half* __restrict__ Kp,
                          const void* __restrict__ mask, float* __restrict__ attn,
                          __half* __restrict__ attn_h) {
    extern __shared__ __align__(16) char dbuf[];
    float* Sbuf = (float*)dbuf;                              // [16][1032]
    __half* Qs = (__half*)(dbuf + 16 * LDS_F * 4);           // [16][72]
    __half* Ks = Qs + 16 * LDK_F;                            // [2][128][72]

    const int z = blockIdx.y;
    const int b = z >> 4;
    const int q0 = blockIdx.x * 16;
    const int tid = threadIdx.x;
    const int w = tid >> 5;
    const int lane = tid & 31;

    const __half* Qb = Qp + (size_t)z * Sc * 64;
    const __half* Kb = Kp + (size_t)z * Sc * 64;

    // Q tile 16x64 = 128 uint4
    if (tid < 128) {
        int r = tid >> 3, c = (tid & 7) * 8;
        *(uint4*)&Qs[r * LDK_F + c] = *(const uint4*)&Qb[(size_t)(q0 + r) * 64 + c];
    }

    // K tile: 128 rows x 64 cols fp16. 2 threads/row, 4 uint4 each.
    const int kr = tid >> 1;
    const int kc = (tid & 1) * 32;

    uint4 kreg[4];
#pragma unroll
    for (int j = 0; j < 4; j++)
        kreg[j] = *(const uint4*)&Kb[(size_t)kr * 64 + kc + j * 8];
#pragma unroll
    for (int j = 0; j < 4; j++)
        *(uint4*)&Ks[kr * LDK_F + kc + j * 8] = kreg[j];
    __syncthreads();

    // Hoist Q fragments (4: one per 16-deep k-step)
    hfrag_a qf[4];
#pragma unroll
    for (int ks = 0; ks < 4; ks++)
        wmma::load_matrix_sync(qf[ks], Qs + ks * 16, LDK_F);

    for (int kt = 0; kt < 8; kt++) {
        if (kt < 7) {
            const size_t gb = (size_t)(kt + 1) * 128 * 64;
#pragma unroll
            for (int j = 0; j < 4; j++)
                kreg[j] = *(const uint4*)&Kb[gb + (size_t)kr * 64 + kc + j * 8];
        }
        const int cur = (kt & 1) * 128 * LDK_F;

        hfrag_c acc;
        wmma::fill_fragment(acc, 0.0f);
#pragma unroll
        for (int ks = 0; ks < 4; ks++) {
            hfrag_bc fb;
            wmma::load_matrix_sync(fb, Ks + cur + (w * 16) * LDK_F + ks * 16, LDK_F);
            wmma::mma_sync(acc, qf[ks], fb, acc);
        }
        wmma::store_matrix_sync(&Sbuf[kt * 128 + w * 16], acc, LDS_F, wmma::mem_row_major);

        if (kt < 7) {
            const int nxt = ((kt + 1) & 1) * 128 * LDK_F;
#pragma unroll
            for (int j = 0; j < 4; j++)
                *(uint4*)&Ks[nxt + kr * LDK_F + kc + j * 8] = kreg[j];
        }
        __syncthreads();
    }

    // ---- softmax: warp w owns rows 2w, 2w+1 ----
    const int mode = g_mask_mode;
    const int* mi = (const int*)mask;
    const unsigned char* mb8 = (const unsigned char*)mask;
    const float* mf = (const float*)mask;

#pragma unroll
    for (int rr = 0; rr < 2; rr++) {
        const int r = w * 2 + rr;
        const int qrow = q0 + r;
        float* Srow = Sbuf + r * LDS_F;
        const size_t mrow = (size_t)b * Sc * Sc + (size_t)qrow * Sc;

        float mx = -3.0e38f;
#pragma unroll
        for (int i = 0; i < 32; i++) {
            int kk = lane + i * 32;
            bool masked;
            if (mode == 0)      masked = (mi[mrow + kk] != 0);
            else if (mode == 2) masked = (mf[mrow + kk] != 0.0f);
            else                masked = (mb8[mrow + kk] != 0);
            float vv = masked ? -1e9f : Srow[kk] * 0.125f;
            Srow[kk] = vv;
            mx = fmaxf(mx, vv);
        }
#pragma unroll
        for (int o = 16; o; o >>= 1) mx = fmaxf(mx, __shfl_xor_sync(0xffffffffu, mx, o));

        float sum = 0.0f;
#pragma unroll
        for (int i = 0; i < 32; i++) {
            int kk = lane + i * 32;
            float e = expf(Srow[kk] - mx);
            Srow[kk] = e;
            sum += e;
        }
#pragma unroll
        for (int o = 16; o; o >>= 1) sum += __shfl_xor_sync(0xffffffffu, sum, o);
        float inv = 1.0f / sum;

        float4* dst = (float4*)(attn + ((size_t)z * Sc + qrow) * Sc);
        __half* dsth = attn_h + ((size_t)z * Sc + qrow) * Sc;
#pragma unroll
        for (int i = 0; i < 8; i++) {
            int k4 = lane + i * 32;
            float4 vv = *(float4*)&Srow[k4 * 4];
            vv.x *= inv; vv.y *= inv; vv.z *= inv; vv.w *= inv;
            dst[k4] = vv;
            cvt_store4_h(dsth + k4 * 4, vv);
        }
    }
}

// ---------------------------------------------------------------------------
// Context: BM=256, BN=64, single fp16, warp tile 32x64 (R7-proven shape).
// ---------------------------------------------------------------------------
__global__ __launch_bounds__(256)
void context_wide(const __half* __restrict__ P, const __half* __restrict__ Vp,
                  __half* __restrict__ C) {
    constexpr int LDA = 24;
    constexpr int LDW = 72;
    constexpr int LDST = 68;

    __shared__ __align__(16) char buf[34816];
    __half* As = (__half*)buf;
    __half* Ws = As + 2 * 256 * LDA;
    float* stg = (float*)buf;

    const int tid = threadIdx.x;
    const int w = tid >> 5;
    const int z = blockIdx.y;
    const int row0 = blockIdx.x * 256;

    const __half* Pb = P + (size_t)z * Sc * Sc;
    const __half* Vb = Vp + (size_t)z * Sc * 64;

    const int ar = tid >> 1, ac = (tid & 1) * 8;
    const int in_b = tid < 128;
    const int wr = tid >> 3, wc = (tid & 7) * 8;

    hfrag_c acc[2][4];
#pragma unroll
    for (int ti = 0; ti < 2; ti++)
#pragma unroll
        for (int tj = 0; tj < 4; tj++) wmma::fill_fragment(acc[ti][tj], 0.0f);

    uint4 pa0, pa1, pb;
    pa0 = *(const uint4*)&Pb[(size_t)(row0 + ar) * Sc + ac];
    pa1 = *(const uint4*)&Pb[(size_t)(row0 + ar + 128) * Sc + ac];
    if (in_b) pb = *(const uint4*)&Vb[(size_t)wr * 64 + wc];
    *(uint4*)&As[ar * LDA + ac] = pa0;
    *(uint4*)&As[(ar + 128) * LDA + ac] = pa1;
    if (in_b) *(uint4*)&Ws[wr * LDW + wc] = pb;
    __syncthreads();

    for (int kt = 0; kt < 64; kt++) {
        if (kt < 63) {
            int kk = (kt + 1) * 16;
            pa0 = *(const uint4*)&Pb[(size_t)(row0 + ar) * Sc + kk + ac];
            pa1 = *(const uint4*)&Pb[(size_t)(row0 + ar + 128) * Sc + kk + ac];
            if (in_b) pb = *(const uint4*)&Vb[(size_t)(kk + wr) * 64 + wc];
        }
        const int cur = kt & 1;
        const int cb = cur * 256 * LDA;
        const int wb = cur * 16 * LDW;

        hfrag_a fa[2];
#pragma unroll
        for (int ti = 0; ti < 2; ti++)
            wmma::load_matrix_sync(fa[ti], As + cb + (w * 32 + ti * 16) * LDA, LDA);
#pragma unroll
        for (int tj = 0; tj < 4; tj++) {
            hfrag_b fb;
            wmma::load_matrix_sync(fb, Ws + wb + tj * 16, LDW);
#pragma unroll
            for (int ti = 0; ti < 2; ti++)
                wmma::mma_sync(acc[ti][tj], fa[ti], fb, acc[ti][tj]);
        }

        if (kt < 63) {
            const int nb = (cur ^ 1) * 256 * LDA;
            const int nw = (cur ^ 1) * 16 * LDW;
            *(uint4*)&As[nb + ar * LDA + ac] = pa0;
            *(uint4*)&As[nb + (ar + 128) * LDA + ac] = pa1;
            if (in_b) *(uint4*)&Ws[nw + wr * LDW + wc] = pb;
        }
        __syncthreads();
    }

    const int b = z >> 4, h = z & 15;
#pragma unroll
    for (int ph = 0; ph < 2; ph++) {
        if ((w >> 2) == ph) {
#pragma unroll
            for (int ti = 0; ti < 2; ti++)
#pragma unroll
                for (int tj = 0; tj < 4; tj++)
                    wmma::store_matrix_sync(&stg[((w & 3) * 32 + ti * 16) * LDST + tj * 16],
                                            acc[ti][tj], LDST, wmma::mem_row_major);
        }
        __syncthreads();
#pragma unroll
        for (int i = tid; i < 2048; i += 256) {
            int r = i >> 4, c4 = (i & 15) * 4;
            int s = row0 + ph * 128 + r;
            float4 vv = *(float4*)&stg[r * LDST + c4];
            cvt_store4_h(C + ((size_t)(b * Sc + s)) * HDc + h * DVc + c4, vv);
        }
        __syncthreads();
    }
}

// ---------------------------------------------------------------------------
// Out-proj: BM=128, BN=128, single fp16, fp32 out (R7-proven shape).
// ---------------------------------------------------------------------------
__global__ __launch_bounds__(256)
void outproj_wide(const __half* __restrict__ Ab, const float* __restrict__ W,
                  const float* __restrict__ bias, float* __restrict__ Cf) {
    constexpr int LDA = 24;
    constexpr int LDW = 136;
    constexpr int LDST = 132;

    __shared__ __align__(16) char buf[33792];
    __half* As = (__half*)buf;
    __half* Ws = As + 2 * 128 * LDA;
    float* stg = (float*)buf;

    const int tid = threadIdx.x;
    const int w = tid >> 5;
    const int wm = w >> 1;
    const int wn = w & 1;
    const int row0 = blockIdx.y * 128;
    const int col0 = blockIdx.x * 128;

    const int br = tid >> 1, bc = (tid & 1) * 8;
    const int wr0 = tid >> 5, wc0 = (tid & 31) * 4;

    hfrag_c acc[2][4];
#pragma unroll
    for (int ti = 0; ti < 2; ti++)
#pragma unroll
        for (int tj = 0; tj < 4; tj++) wmma::fill_fragment(acc[ti][tj], 0.0f);

    uint4 pa;
    float4 rw0, rw1;
    pa = *(const uint4*)&Ab[(size_t)(row0 + br) * Dc + bc];
    rw0 = *(const float4*)&W[(size_t)wr0 * Dc + col0 + wc0];
    rw1 = *(const float4*)&W[(size_t)(wr0 + 8) * Dc + col0 + wc0];
    *(uint4*)&As[br * LDA + bc] = pa;
    cvt_store4_h(Ws + wr0 * LDW + wc0, rw0);
    cvt_store4_h(Ws + (wr0 + 8) * LDW + wc0, rw1);
    __syncthreads();

    for (int kt = 0; kt < 64; kt++) {
        if (kt < 63) {
            int kk = (kt + 1) * 16;
            pa = *(const uint4*)&Ab[(size_t)(row0 + br) * Dc + kk + bc];
            rw0 = *(const float4*)&W[(size_t)(kk + wr0) * Dc + col0 + wc0];
            rw1 = *(const float4*)&W[(size_t)(kk + wr0 + 8) * Dc + col0 + wc0];
        }
        const int cur = kt & 1;
        const int cb = cur * 128 * LDA;
        const int wb = cur * 16 * LDW;

        hfrag_a fa[2];
#pragma unroll
        for (int ti = 0; ti < 2; ti++)
            wmma::load_matrix_sync(fa[ti], As + cb + (wm * 32 + ti * 16) * LDA, LDA);
#pragma unroll
        for (int tj = 0; tj < 4; tj++) {
            hfrag_b fb;
            wmma::load_matrix_sync(fb, Ws + wb + wn * 64 + tj * 16, LDW);
#pragma unroll
            for (int ti = 0; ti < 2; ti++)
                wmma::mma_sync(acc[ti][tj], fa[ti], fb, acc[ti][tj]);
        }

        if (kt < 63) {
            const int nb = (cur ^ 1) * 128 * LDA;
            const int nw = (cur ^ 1) * 16 * LDW;
            *(uint4*)&As[nb + br * LDA + bc] = pa;
            cvt_store4_h(Ws + nw + wr0 * LDW + wc0, rw0);
            cvt_store4_h(Ws + nw + (wr0 + 8) * LDW + wc0, rw1);
        }
        __syncthreads();
    }

#pragma unroll
    for (int ph = 0; ph < 2; ph++) {
        if ((wm >> 1) == ph) {
#pragma unroll
            for (int ti = 0; ti < 2; ti++)
#pragma unroll
                for (int tj = 0; tj < 4; tj++)
                    wmma::store_matrix_sync(&stg[((wm & 1) * 32 + ti * 16) * LDST + wn * 64 + tj * 16],
                                            acc[ti][tj], LDST, wmma::mem_row_major);
        }
        __syncthreads();
#pragma unroll
        for (int i = tid; i < 2048; i += 256) {
            int r = i >> 5, c4 = (i & 31) * 4;
            int m = row0 + ph * 64 + r;
            int col = col0 + c4;
            float4 vv = *(float4*)&stg[r * LDST + c4];
            float4 bi = *(const float4*)&bias[col];
            vv.x += bi.x; vv.y += bi.y; vv.z += bi.z; vv.w += bi.w;
            *(float4*)&Cf[(size_t)m * Dc + col] = vv;
        }
        __syncthreads();
    }
}

// ---------------------------------------------------------------------------
// Fused residual add + LayerNorm
// ---------------------------------------------------------------------------
__global__ __launch_bounds__(256)
void layernorm_kernel(const float* __restrict__ x, const float* __restrict__ resid,
                      float* __restrict__ out) {
    const size_t row = blockIdx.x;
    const float4* xr = (const float4*)(x + row * Dc);
    const float4* rr = (const float4*)(resid + row * Dc);
    float4* orow = (float4*)(out + row * Dc);
    const int tid = threadIdx.x;
    const int lane = tid & 31, wid = tid >> 5;
    __shared__ float sm[16];

    float4 a = xr[tid], b = rr[tid];
    float4 v = make_float4(a.x + b.x, a.y + b.y, a.z + b.z, a.w + b.w);
    float s = (v.x + v.y) + (v.z + v.w);
#pragma unroll
    for (int o = 16; o; o >>= 1) s += __shfl_xor_sync(0xffffffffu, s, o);
    if (lane == 0) sm[wid] = s;
    __syncthreads();
    float tot = 0.0f;
#pragma unroll
    for (int i = 0; i < 8; i++) tot += sm[i];
    float mean = tot * (1.0f / 1024.0f);

    float dx = v.x - mean, dy = v.y - mean, dz = v.z - mean, dw = v.w - mean;
    float vs = (dx * dx + dy * dy) + (dz * dz + dw * dw);
#pragma unroll
    for (int o = 16; o; o >>= 1) vs += __shfl_xor_sync(0xffffffffu, vs, o);
    if (lane == 0) sm[8 + wid] = vs;
    __syncthreads();
    float vtot = 0.0f;
#pragma unroll
    for (int i = 0; i < 8; i++) vtot += sm[8 + i];
    float inv = rsqrtf(vtot * (1.0f / 1024.0f) + 1e-5f);
    orow[tid] = make_float4(dx * inv, dy * inv, dz * inv, dw * inv);
}

// ---------------------------------------------------------------------------
// Launch
// ---------------------------------------------------------------------------
extern "C" void kernel_launch(void* const* d_in, const int* in_sizes, int n_in,
                              void* d_out, int out_size) {
    const float* q    = (const float*)d_in[0];
    const float* k    = (const float*)d_in[1];
    const float* v    = (const float*)d_in[2];
    const void*  mask = d_in[3];
    const float* Wq   = (const float*)d_in[4];
    const float* bq   = (const float*)d_in[5];
    const float* Wk   = (const float*)d_in[6];
    const float* bk   = (const float*)d_in[7];
    const float* Wv   = (const float*)d_in[8];
    const float* bv   = (const float*)d_in[9];
    const float* Wo   = (const float*)d_in[10];
    const float* bo   = (const float*)d_in[11];
    float* out = (float*)d_out;

    __half *Qp, *Kp, *Vp, *ctx, *attn_h;
    float *obuf, *attn_fb;
    cudaGetSymbolAddress((void**)&Qp, g_Qp);
    cudaGetSymbolAddress((void**)&Kp, g_Kp);
    cudaGetSymbolAddress((void**)&Vp, g_Vp);
    cudaGetSymbolAddress((void**)&ctx, g_ctx);
    cudaGetSymbolAddress((void**)&attn_h, g_attn_h);
    cudaGetSymbolAddress((void**)&obuf, g_obuf);
    cudaGetSymbolAddress((void**)&attn_fb, g_attn_fb);

    const long long LN_ELEMS = (long long)Mc * Dc;
    const long long ATTN_ELEMS = (long long)Bc * Hc * Sc * Sc;
    float* attn = ((long long)out_size >= LN_ELEMS + ATTN_ELEMS)
                      ? (out + (size_t)LN_ELEMS)
                      : attn_fb;

    static int smem_set = 0;
    if (!smem_set) {
        cudaFuncSetAttribute(fused_scores_softmax,
                             cudaFuncAttributeMaxDynamicSharedMemorySize, FUSED_SMEM);
        smem_set = 1;
    }

    detect_mask_kernel<<<1, 1>>>((const unsigned int*)mask);

    // Merged QKV projections, single fp16 (z: 0=Q, 1=K, 2=V)
    qkv_proj<<<dim3(8, 32, 3), 256>>>(q, k, v, Wq, Wk, Wv, bq, bk, bv, Qp, Kp, Vp);

    // Fused scores + mask + softmax -> fp32 probs (output) + fp16 probs
    fused_scores_softmax<<<dim3(64, Bc * Hc), 256, FUSED_SMEM>>>(Qp, Kp, mask, attn, attn_h);

    // Context (fp16 probs @ fp16 V) -> fp16 ctx plane
    context_wide<<<dim3(4, 64), 256>>>(attn_h, Vp, ctx);

    // Output projection (fp16 A, fp32 out)
    outproj_wide<<<dim3(8, 32), 256>>>(ctx, Wo, bo, obuf);

    // Residual + LayerNorm
    layernorm_kernel<<<Mc, 256>>>(obuf, q, out);
}

// round 15
// speedup vs baseline: 1.0934x; 1.0934x over previous
#include <cuda_runtime.h>
#include <cuda_fp16.h>
#include <mma.h>
#include <cstddef>

using namespace nvcuda;

#define Bc 4
#define Sc 1024
#define Dc 1024
#define Hc 16
#define DKc 64
#define DVc 64
#define Mc (Bc * Sc)
#define HDc (Hc * DKc)
#define QP_ELEMS (Mc * HDc)

// ---------------- Static device scratch (fp16) ----------------
__device__ __half g_Qp[QP_ELEMS];                    // [B,H,S,64]
__device__ __half g_Kp[QP_ELEMS];
__device__ __half g_Vp[QP_ELEMS];
__device__ __half g_ctx[Mc * HDc];                   // [B,S,1024]
__device__ __half g_attn_h[(size_t)Bc * Hc * Sc * Sc]; // fp16 probs
__device__ float g_obuf[Mc * Dc];
__device__ float g_attn_fb[(size_t)Bc * Hc * Sc * Sc];
__device__ int   g_mask_mode;

using hfrag_a  = wmma::fragment<wmma::matrix_a, 16, 16, 16, __half, wmma::row_major>;
using hfrag_b  = wmma::fragment<wmma::matrix_b, 16, 16, 16, __half, wmma::row_major>;
using hfrag_bc = wmma::fragment<wmma::matrix_b, 16, 16, 16, __half, wmma::col_major>;
using hfrag_c  = wmma::fragment<wmma::accumulator, 16, 16, 16, float>;

__device__ __forceinline__ void cvt_store4_h(__half* d, float4 v) {
    d[0] = __float2half(v.x);
    d[1] = __float2half(v.y);
    d[2] = __float2half(v.z);
    d[3] = __float2half(v.w);
}

// ---------------------------------------------------------------------------
__global__ void detect_mask_kernel(const unsigned int* __restrict__ m) {
    bool allint = true, allfloat = true;
    for (int i = 0; i < 1024; i++) {
        unsigned int w = m[i];
        if (w > 1u) allint = false;
        if (w != 0u && w != 0x3F800000u) allfloat = false;
    }
    g_mask_mode = allint ? 0 : (allfloat ? 2 : 1);
}

// ---------------------------------------------------------------------------
// Merged QKV projection (uniform single-fp16): grid z = 0(Q), 1(K), 2(V).
// BM=128, BN=128, BK=16, warp tile 32x64 (2x4), double-buffered smem.
// ---------------------------------------------------------------------------
__global__ __launch_bounds__(256)
void qkv_proj(const float* __restrict__ q, const float* __restrict__ k,
              const float* __restrict__ v,
              const float* __restrict__ Wq, const float* __restrict__ Wk,
              const float* __restrict__ Wv,
              const float* __restrict__ bq, const float* __restrict__ bk,
              const float* __restrict__ bv,
              __half* __restrict__ Qp, __half* __restrict__ Kp,
              __half* __restrict__ Vp) {
    constexpr int LDA = 24;
    constexpr int LDW = 136;
    constexpr int LDST = 132;

    __shared__ __align__(16) char buf[33792];
    __half* As = (__half*)buf;          // [2][128][24]
    __half* Ws = As + 2 * 128 * LDA;    // [2][16][136]
    float* stg = (float*)buf;           // [64][132] epilogue reuse

    const int z = blockIdx.z;
    const float* A    = (z == 0) ? q  : (z == 1) ? k  : v;
    const float* W    = (z == 0) ? Wq : (z == 1) ? Wk : Wv;
    const float* bias = (z == 0) ? bq : (z == 1) ? bk : bv;
    __half* C         = (z == 0) ? Qp : (z == 1) ? Kp : Vp;

    const int tid = threadIdx.x;
    const int w = tid >> 5;
    const int wm = w >> 1;
    const int wn = w & 1;
    const int row0 = blockIdx.y * 128;
    const int col0 = blockIdx.x * 128;

    const int ar = tid >> 2, ac = (tid & 3) * 4;
    const int wr0 = tid >> 5, wc0 = (tid & 31) * 4;

    hfrag_c acc[2][4];
#pragma unroll
    for (int ti = 0; ti < 2; ti++)
#pragma unroll
        for (int tj = 0; tj < 4; tj++) wmma::fill_fragment(acc[ti][tj], 0.0f);

    float4 ra0, ra1, rw0, rw1;
    ra0 = *(const float4*)&A[(size_t)(row0 + ar) * Dc + ac];
    ra1 = *(const float4*)&A[(size_t)(row0 + ar + 64) * Dc + ac];
    rw0 = *(const float4*)&W[(size_t)wr0 * HDc + col0 + wc0];
    rw1 = *(const float4*)&W[(size_t)(wr0 + 8) * HDc + col0 + wc0];
    cvt_store4_h(As + ar * LDA + ac, ra0);
    cvt_store4_h(As + (ar + 64) * LDA + ac, ra1);
    cvt_store4_h(Ws + wr0 * LDW + wc0, rw0);
    cvt_store4_h(Ws + (wr0 + 8) * LDW + wc0, rw1);
    __syncthreads();

    for (int kt = 0; kt < 64; kt++) {
        if (kt < 63) {
            int kk = (kt + 1) * 16;
            ra0 = *(const float4*)&A[(size_t)(row0 + ar) * Dc + kk + ac];
            ra1 = *(const float4*)&A[(size_t)(row0 + ar + 64) * Dc + kk + ac];
            rw0 = *(const float4*)&W[(size_t)(kk + wr0) * HDc + col0 + wc0];
            rw1 = *(const float4*)&W[(size_t)(kk + wr0 + 8) * HDc + col0 + wc0];
        }
        const int cur = kt & 1;
        const int cb = cur * 128 * LDA;
        const int wb = cur * 16 * LDW;

        hfrag_a fa[2];
#pragma unroll
        for (int ti = 0; ti < 2; ti++)
            wmma::load_matrix_sync(fa[ti], As + cb + (wm * 32 + ti * 16) * LDA, LDA);
#pragma unroll
        for (int tj = 0; tj < 4; tj++) {
            hfrag_b fb;
            wmma::load_matrix_sync(fb, Ws + wb + wn * 64 + tj * 16, LDW);
#pragma unroll
            for (int ti = 0; ti < 2; ti++)
                wmma::mma_sync(acc[ti][tj], fa[ti], fb, acc[ti][tj]);
        }

        if (kt < 63) {
            const int nb = (cur ^ 1) * 128 * LDA;
            const int nw = (cur ^ 1) * 16 * LDW;
            cvt_store4_h(As + nb + ar * LDA + ac, ra0);
            cvt_store4_h(As + nb + (ar + 64) * LDA + ac, ra1);
            cvt_store4_h(Ws + nw + wr0 * LDW + wc0, rw0);
            cvt_store4_h(Ws + nw + (wr0 + 8) * LDW + wc0, rw1);
        }
        __syncthreads();
    }

#pragma unroll
    for (int ph = 0; ph < 2; ph++) {
        if ((wm >> 1) == ph) {
#pragma unroll
            for (int ti = 0; ti < 2; ti++)
#pragma unroll
                for (int tj = 0; tj < 4; tj++)
                    wmma::store_matrix_sync(&stg[((wm & 1) * 32 + ti * 16) * LDST + wn * 64 + tj * 16],
                                            acc[ti][tj], LDST, wmma::mem_row_major);
        }
        __syncthreads();
#pragma unroll
        for (int i = tid; i < 2048; i += 256) {
            int r = i >> 5, c4 = (i & 31) * 4;
            int m = row0 + ph * 64 + r;
            int col = col0 + c4;
            float4 vv = *(float4*)&stg[r * LDST + c4];
            float4 bi = *(const float4*)&bias[col];
            vv.x += bi.x; vv.y += bi.y; vv.z += bi.z; vv.w += bi.w;
            int b = m >> 10, s = m & 1023, h = col >> 6, d = col & 63;
            cvt_store4_h(C + (((size_t)b * Hc + h) * Sc + s) * 64 + d, vv);
        }
        __syncthreads();
    }
}

// ---------------------------------------------------------------------------
// Scores (raw, unmasked, unscaled): 128x128 tile per block, warp tile 32x64.
// Accumulators stored DIRECTLY to gmem (ld=1024). Mask+scale applied by
// softmax. smem 37KB -> good occupancy, no epilogue staging.
// ---------------------------------------------------------------------------
__global__ __launch_bounds__(256)
void scores_big(const __half* __restrict__ Qp, const __half* __restrict__ Kp,
                float* __restrict__ attn) {
    constexpr int LDT = 72;
    __shared__ __align__(16) __half Qs[128 * LDT];
    __shared__ __align__(16) __half Ks[128 * LDT];

    const int z = blockIdx.z;
    const int q0 = blockIdx.y * 128;
    const int k0 = blockIdx.x * 128;
    const int tid = threadIdx.x;
    const int w = tid >> 5;
    const int wm = w & 3;       // 4 row groups of 32
    const int wn = w >> 2;      // 2 col groups of 64

    const size_t zb = (size_t)z * Sc * 64;

    // load Q,K tiles: 128x64 fp16 = 1024 uint4 each; 4/thread/tile
#pragma unroll
    for (int i = tid; i < 1024; i += 256) {
        int r = i >> 3, c = (i & 7) * 8;
        *(uint4*)&Qs[r * LDT + c] = *(const uint4*)&Qp[zb + (size_t)(q0 + r) * 64 + c];
        *(uint4*)&Ks[r * LDT + c] = *(const uint4*)&Kp[zb + (size_t)(k0 + r) * 64 + c];
    }
    __syncthreads();

    hfrag_c acc[2][4];
#pragma unroll
    for (int ti = 0; ti < 2; ti++)
#pragma unroll
        for (int tj = 0; tj < 4; tj++) wmma::fill_fragment(acc[ti][tj], 0.0f);

#pragma unroll
    for (int ks = 0; ks < 4; ks++) {
        const int kb = ks * 16;
        hfrag_a fa[2];
#pragma unroll
        for (int ti = 0; ti < 2; ti++)
            wmma::load_matrix_sync(fa[ti], Qs + (wm * 32 + ti * 16) * LDT + kb, LDT);
#pragma unroll
        for (int tj = 0; tj < 4; tj++) {
            hfrag_bc fb;
            wmma::load_matrix_sync(fb, Ks + (wn * 64 + tj * 16) * LDT + kb, LDT);
#pragma unroll
            for (int ti = 0; ti < 2; ti++)
                wmma::mma_sync(acc[ti][tj], fa[ti], fb, acc[ti][tj]);
        }
    }

    // direct global store (raw scores)
#pragma unroll
    for (int ti = 0; ti < 2; ti++)
#pragma unroll
        for (int tj = 0; tj < 4; tj++) {
            int qq = q0 + wm * 32 + ti * 16;
            int kk = k0 + wn * 64 + tj * 16;
            wmma::store_matrix_sync(&attn[((size_t)z * Sc + qq) * Sc + kk],
                                    acc[ti][tj], Sc, wmma::mem_row_major);
        }
}

// ---------------------------------------------------------------------------
// Softmax with fused mask + scale; in place on raw scores; emits fp16 probs.
// ---------------------------------------------------------------------------
__global__ __launch_bounds__(256)
void softmax_kernel(float* __restrict__ attn, __half* __restrict__ attn_h,
                    const void* __restrict__ mask) {
    const size_t row = blockIdx.x;       // z*Sc + q
    const int b = (int)(row >> 14);      // / (Hc*Sc)
    const int qrow = (int)(row & 1023);
    float4* p = (float4*)(attn + row * Sc);
    __half* ph = attn_h + row * Sc;
    const int tid = threadIdx.x;
    const int lane = tid & 31, wid = tid >> 5;
    __shared__ float sm[16];

    const size_t mrow = ((size_t)b * Sc + qrow) * Sc;
    const int mode = g_mask_mode;

    float4 v = p[tid];
    // apply scale + mask
    {
        bool m0, m1, m2, m3;
        if (mode == 0) {
            int4 mi = *(const int4*)((const int*)mask + mrow + tid * 4);
            m0 = mi.x != 0; m1 = mi.y != 0; m2 = mi.z != 0; m3 = mi.w != 0;
        } else if (mode == 2) {
            float4 mf = *(const float4*)((const float*)mask + mrow + tid * 4);
            m0 = mf.x != 0.0f; m1 = mf.y != 0.0f; m2 = mf.z != 0.0f; m3 = mf.w != 0.0f;
        } else {
            uchar4 mb = *(const uchar4*)((const unsigned char*)mask + mrow + tid * 4);
            m0 = mb.x != 0; m1 = mb.y != 0; m2 = mb.z != 0; m3 = mb.w != 0;
        }
        v.x = m0 ? -1e9f : v.x * 0.125f;
        v.y = m1 ? -1e9f : v.y * 0.125f;
        v.z = m2 ? -1e9f : v.z * 0.125f;
        v.w = m3 ? -1e9f : v.w * 0.125f;
    }

    float mx = fmaxf(fmaxf(v.x, v.y), fmaxf(v.z, v.w));
#pragma unroll
    for (int o = 16; o; o >>= 1) mx = fmaxf(mx, __shfl_xor_sync(0xffffffffu, mx, o));
    if (lane == 0) sm[wid] = mx;
    __syncthreads();
    float m = sm[0];
#pragma unroll
    for (int i = 1; i < 8; i++) m = fmaxf(m, sm[i]);

    v.x = expf(v.x - m); v.y = expf(v.y - m);
    v.z = expf(v.z - m); v.w = expf(v.w - m);
    float s = (v.x + v.y) + (v.z + v.w);
#pragma unroll
    for (int o = 16; o; o >>= 1) s += __shfl_xor_sync(0xffffffffu, s, o);
    if (lane == 0) sm[8 + wid] = s;
    __syncthreads();
    float tot = 0.0f;
#pragma unroll
    for (int i = 0; i < 8; i++) tot += sm[8 + i];
    float inv = 1.0f / tot;
    v.x *= inv; v.y *= inv; v.z *= inv; v.w *= inv;
    p[tid] = v;
    cvt_store4_h(ph + tid * 4, v);
}

// ---------------------------------------------------------------------------
// Context: BM=256, BN=64, single fp16, warp tile 32x64 (R7-proven shape).
// ---------------------------------------------------------------------------
__global__ __launch_bounds__(256)
void context_wide(const __half* __restrict__ P, const __half* __restrict__ Vp,
                  __half* __restrict__ C) {
    constexpr int LDA = 24;
    constexpr int LDW = 72;
    constexpr int LDST = 68;

    __shared__ __align__(16) char buf[34816];
    __half* As = (__half*)buf;
    __half* Ws = As + 2 * 256 * LDA;
    float* stg = (float*)buf;

    const int tid = threadIdx.x;
    const int w = tid >> 5;
    const int z = blockIdx.y;
    const int row0 = blockIdx.x * 256;

    const __half* Pb = P + (size_t)z * Sc * Sc;
    const __half* Vb = Vp + (size_t)z * Sc * 64;

    const int ar = tid >> 1, ac = (tid & 1) * 8;
    const int in_b = tid < 128;
    const int wr = tid >> 3, wc = (tid & 7) * 8;

    hfrag_c acc[2][4];
#pragma unroll
    for (int ti = 0; ti < 2; ti++)
#pragma unroll
        for (int tj = 0; tj < 4; tj++) wmma::fill_fragment(acc[ti][tj], 0.0f);

    uint4 pa0, pa1, pb;
    pa0 = *(const uint4*)&Pb[(size_t)(row0 + ar) * Sc + ac];
    pa1 = *(const uint4*)&Pb[(size_t)(row0 + ar + 128) * Sc + ac];
    if (in_b) pb = *(const uint4*)&Vb[(size_t)wr * 64 + wc];
    *(uint4*)&As[ar * LDA + ac] = pa0;
    *(uint4*)&As[(ar + 128) * LDA + ac] = pa1;
    if (in_b) *(uint4*)&Ws[wr * LDW + wc] = pb;
    __syncthreads();

    for (int kt = 0; kt < 64; kt++) {
        if (kt < 63) {
            int kk = (kt + 1) * 16;
            pa0 = *(const uint4*)&Pb[(size_t)(row0 + ar) * Sc + kk + ac];
            pa1 = *(const uint4*)&Pb[(size_t)(row0 + ar + 128) * Sc + kk + ac];
            if (in_b) pb = *(const uint4*)&Vb[(size_t)(kk + wr) * 64 + wc];
        }
        const int cur = kt & 1;
        const int cb = cur * 256 * LDA;
        const int wb = cur * 16 * LDW;

        hfrag_a fa[2];
#pragma unroll
        for (int ti = 0; ti < 2; ti++)
            wmma::load_matrix_sync(fa[ti], As + cb + (w * 32 + ti * 16) * LDA, LDA);
#pragma unroll
        for (int tj = 0; tj < 4; tj++) {
            hfrag_b fb;
            wmma::load_matrix_sync(fb, Ws + wb + tj * 16, LDW);
#pragma unroll
            for (int ti = 0; ti < 2; ti++)
                wmma::mma_sync(acc[ti][tj], fa[ti], fb, acc[ti][tj]);
        }

        if (kt < 63) {
            const int nb = (cur ^ 1) * 256 * LDA;
            const int nw = (cur ^ 1) * 16 * LDW;
            *(uint4*)&As[nb + ar * LDA + ac] = pa0;
            *(uint4*)&As[nb + (ar + 128) * LDA + ac] = pa1;
            if (in_b) *(uint4*)&Ws[nw + wr * LDW + wc] = pb;
        }
        __syncthreads();
    }

    const int b = z >> 4, h = z & 15;
#pragma unroll
    for (int ph = 0; ph < 2; ph++) {
        if ((w >> 2) == ph) {
#pragma unroll
            for (int ti = 0; ti < 2; ti++)
#pragma unroll
                for (int tj = 0; tj < 4; tj++)
                    wmma::store_matrix_sync(&stg[((w & 3) * 32 + ti * 16) * LDST + tj * 16],
                                            acc[ti][tj], LDST, wmma::mem_row_major);
        }
        __syncthreads();
#pragma unroll
        for (int i = tid; i < 2048; i += 256) {
            int r = i >> 4, c4 = (i & 15) * 4;
            int s = row0 + ph * 128 + r;
            float4 vv = *(float4*)&stg[r * LDST + c4];
            cvt_store4_h(C + ((size_t)(b * Sc + s)) * HDc + h * DVc + c4, vv);
        }
        __syncthreads();
    }
}

// ---------------------------------------------------------------------------
// Out-proj: BM=128, BN=128, single fp16, fp32 out (R7-proven shape).
// ---------------------------------------------------------------------------
__global__ __launch_bounds__(256)
void outproj_wide(const __half* __restrict__ Ab, const float* __restrict__ W,
                  const float* __restrict__ bias, float* __restrict__ Cf) {
    constexpr int LDA = 24;
    constexpr int LDW = 136;
    constexpr int LDST = 132;

    __shared__ __align__(16) char buf[33792];
    __half* As = (__half*)buf;
    __half* Ws = As + 2 * 128 * LDA;
    float* stg = (float*)buf;

    const int tid = threadIdx.x;
    const int w = tid >> 5;
    const int wm = w >> 1;
    const int wn = w & 1;
    const int row0 = blockIdx.y * 128;
    const int col0 = blockIdx.x * 128;

    const int br = tid >> 1, bc = (tid & 1) * 8;
    const int wr0 = tid >> 5, wc0 = (tid & 31) * 4;

    hfrag_c acc[2][4];
#pragma unroll
    for (int ti = 0; ti < 2; ti++)
#pragma unroll
        for (int tj = 0; tj < 4; tj++) wmma::fill_fragment(acc[ti][tj], 0.0f);

    uint4 pa;
    float4 rw0, rw1;
    pa = *(const uint4*)&Ab[(size_t)(row0 + br) * Dc + bc];
    rw0 = *(const float4*)&W[(size_t)wr0 * Dc + col0 + wc0];
    rw1 = *(const float4*)&W[(size_t)(wr0 + 8) * Dc + col0 + wc0];
    *(uint4*)&As[br * LDA + bc] = pa;
    cvt_store4_h(Ws + wr0 * LDW + wc0, rw0);
    cvt_store4_h(Ws + (wr0 + 8) * LDW + wc0, rw1);
    __syncthreads();

    for (int kt = 0; kt < 64; kt++) {
        if (kt < 63) {
            int kk = (kt + 1) * 16;
            pa = *(const uint4*)&Ab[(size_t)(row0 + br) * Dc + kk + bc];
            rw0 = *(const float4*)&W[(size_t)(kk + wr0) * Dc + col0 + wc0];
            rw1 = *(const float4*)&W[(size_t)(kk + wr0 + 8) * Dc + col0 + wc0];
        }
        const int cur = kt & 1;
        const int cb = cur * 128 * LDA;
        const int wb = cur * 16 * LDW;

        hfrag_a fa[2];
#pragma unroll
        for (int ti = 0; ti < 2; ti++)
            wmma::load_matrix_sync(fa[ti], As + cb + (wm * 32 + ti * 16) * LDA, LDA);
#pragma unroll
        for (int tj = 0; tj < 4; tj++) {
            hfrag_b fb;
            wmma::load_matrix_sync(fb, Ws + wb + wn * 64 + tj * 16, LDW);
#pragma unroll
            for (int ti = 0; ti < 2; ti++)
                wmma::mma_sync(acc[ti][tj], fa[ti], fb, acc[ti][tj]);
        }

        if (kt < 63) {
            const int nb = (cur ^ 1) * 128 * LDA;
            const int nw = (cur ^ 1) * 16 * LDW;
            *(uint4*)&As[nb + br * LDA + bc] = pa;
            cvt_store4_h(Ws + nw + wr0 * LDW + wc0, rw0);
            cvt_store4_h(Ws + nw + (wr0 + 8) * LDW + wc0, rw1);
        }
        __syncthreads();
    }

#pragma unroll
    for (int ph = 0; ph < 2; ph++) {
        if ((wm >> 1) == ph) {
#pragma unroll
            for (int ti = 0; ti < 2; ti++)
#pragma unroll
                for (int tj = 0; tj < 4; tj++)
                    wmma::store_matrix_sync(&stg[((wm & 1) * 32 + ti * 16) * LDST + wn * 64 + tj * 16],
                                            acc[ti][tj], LDST, wmma::mem_row_major);
        }
        __syncthreads();
#pragma unroll
        for (int i = tid; i < 2048; i += 256) {
            int r = i >> 5, c4 = (i & 31) * 4;
            int m = row0 + ph * 64 + r;
            int col = col0 + c4;
            float4 vv = *(float4*)&stg[r * LDST + c4];
            float4 bi = *(const float4*)&bias[col];
            vv.x += bi.x; vv.y += bi.y; vv.z += bi.z; vv.w += bi.w;
            *(float4*)&Cf[(size_t)m * Dc + col] = vv;
        }
        __syncthreads();
    }
}

// ---------------------------------------------------------------------------
// Fused residual add + LayerNorm
// ---------------------------------------------------------------------------
__global__ __launch_bounds__(256)
void layernorm_kernel(const float* __restrict__ x, const float* __restrict__ resid,
                      float* __restrict__ out) {
    const size_t row = blockIdx.x;
    const float4* xr = (const float4*)(x + row * Dc);
    const float4* rr = (const float4*)(resid + row * Dc);
    float4* orow = (float4*)(out + row * Dc);
    const int tid = threadIdx.x;
    const int lane = tid & 31, wid = tid >> 5;
    __shared__ float sm[16];

    float4 a = xr[tid], b = rr[tid];
    float4 v = make_float4(a.x + b.x, a.y + b.y, a.z + b.z, a.w + b.w);
    float s = (v.x + v.y) + (v.z + v.w);
#pragma unroll
    for (int o = 16; o; o >>= 1) s += __shfl_xor_sync(0xffffffffu, s, o);
    if (lane == 0) sm[wid] = s;
    __syncthreads();
    float tot = 0.0f;
#pragma unroll
    for (int i = 0; i < 8; i++) tot += sm[i];
    float mean = tot * (1.0f / 1024.0f);

    float dx = v.x - mean, dy = v.y - mean, dz = v.z - mean, dw = v.w - mean;
    float vs = (dx * dx + dy * dy) + (dz * dz + dw * dw);
#pragma unroll
    for (int o = 16; o; o >>= 1) vs += __shfl_xor_sync(0xffffffffu, vs, o);
    if (lane == 0) sm[8 + wid] = vs;
    __syncthreads();
    float vtot = 0.0f;
#pragma unroll
    for (int i = 0; i < 8; i++) vtot += sm[8 + i];
    float inv = rsqrtf(vtot * (1.0f / 1024.0f) + 1e-5f);
    orow[tid] = make_float4(dx * inv, dy * inv, dz * inv, dw * inv);
}

// ---------------------------------------------------------------------------
// Launch
// ---------------------------------------------------------------------------
extern "C" void kernel_launch(void* const* d_in, const int* in_sizes, int n_in,
                              void* d_out, int out_size) {
    const float* q    = (const float*)d_in[0];
    const float* k    = (const float*)d_in[1];
    const float* v    = (const float*)d_in[2];
    const void*  mask = d_in[3];
    const float* Wq   = (const float*)d_in[4];
    const float* bq   = (const float*)d_in[5];
    const float* Wk   = (const float*)d_in[6];
    const float* bk   = (const float*)d_in[7];
    const float* Wv   = (const float*)d_in[8];
    const float* bv   = (const float*)d_in[9];
    const float* Wo   = (const float*)d_in[10];
    const float* bo   = (const float*)d_in[11];
    float* out = (float*)d_out;

    __half *Qp, *Kp, *Vp, *ctx, *attn_h;
    float *obuf, *attn_fb;
    cudaGetSymbolAddress((void**)&Qp, g_Qp);
    cudaGetSymbolAddress((void**)&Kp, g_Kp);
    cudaGetSymbolAddress((void**)&Vp, g_Vp);
    cudaGetSymbolAddress((void**)&ctx, g_ctx);
    cudaGetSymbolAddress((void**)&attn_h, g_attn_h);
    cudaGetSymbolAddress((void**)&obuf, g_obuf);
    cudaGetSymbolAddress((void**)&attn_fb, g_attn_fb);

    const long long LN_ELEMS = (long long)Mc * Dc;
    const long long ATTN_ELEMS = (long long)Bc * Hc * Sc * Sc;
    float* attn = ((long long)out_size >= LN_ELEMS + ATTN_ELEMS)
                      ? (out + (size_t)LN_ELEMS)
                      : attn_fb;

    detect_mask_kernel<<<1, 1>>>((const unsigned int*)mask);

    // Merged QKV projections, single fp16 (z: 0=Q, 1=K, 2=V)
    qkv_proj<<<dim3(8, 32, 3), 256>>>(q, k, v, Wq, Wk, Wv, bq, bk, bv, Qp, Kp, Vp);

    // Raw scores (128x128 tiles, direct gmem store)
    scores_big<<<dim3(8, 8, Bc * Hc), 256>>>(Qp, Kp, attn);

    // Softmax with fused mask+scale, in place; emits fp16 probs
    softmax_kernel<<<Bc * Hc * Sc, 256>>>(attn, attn_h, mask);

    // Context (fp16 probs @ fp16 V) -> fp16 ctx plane
    context_wide<<<dim3(4, 64), 256>>>(attn_h, Vp, ctx);

    // Output projection (fp16 A, fp32 out)
    outproj_wide<<<dim3(8, 32), 256>>>(ctx, Wo, bo, obuf);

    // Residual + LayerNorm
    layernorm_kernel<<<Mc, 256>>>(obuf, q, out);
}

// round 16
// speedup vs baseline: 1.1352x; 1.0383x over previous
#include <cuda_runtime.h>
#include <cuda_fp16.h>
#include <mma.h>
#include <cstddef>

using namespace nvcuda;

#define Bc 4
#define Sc 1024
#define Dc 1024
#define Hc 16
#define DKc 64
#define DVc 64
#define Mc (Bc * Sc)
#define HDc (Hc * DKc)
#define QP_ELEMS (Mc * HDc)

// ---------------- Static device scratch (fp16) ----------------
__device__ __half g_Qp[QP_ELEMS];                    // [B,H,S,64]
__device__ __half g_Kp[QP_ELEMS];
__device__ __half g_Vp[QP_ELEMS];
__device__ __half g_ctx[Mc * HDc];                   // [B,S,1024]
__device__ __half g_attn_h[(size_t)Bc * Hc * Sc * Sc]; // fp16 probs
__device__ float g_obuf[Mc * Dc];
__device__ float g_attn_fb[(size_t)Bc * Hc * Sc * Sc];
__device__ int   g_mask_mode;

using hfrag_a  = wmma::fragment<wmma::matrix_a, 16, 16, 16, __half, wmma::row_major>;
using hfrag_b  = wmma::fragment<wmma::matrix_b, 16, 16, 16, __half, wmma::row_major>;
using hfrag_bc = wmma::fragment<wmma::matrix_b, 16, 16, 16, __half, wmma::col_major>;
using hfrag_c  = wmma::fragment<wmma::accumulator, 16, 16, 16, float>;

// Packed fp32x4 -> fp16x4 store: 2x cvt.rn.f16x2.f32 + ONE 8-byte store.
// Bit-identical rounding to __float2half (rn). Requires d 8B-aligned
// (true at every call site: 4-half-multiple column offsets, 48B/272B rows).
__device__ __forceinline__ void cvt_store4_h(__half* d, float4 v) {
    union { __half2 h2[2]; uint2 u; } pk;
    pk.h2[0] = __floats2half2_rn(v.x, v.y);
    pk.h2[1] = __floats2half2_rn(v.z, v.w);
    *(uint2*)d = pk.u;
}

// ---------------------------------------------------------------------------
__global__ void detect_mask_kernel(const unsigned int* __restrict__ m) {
    bool allint = true, allfloat = true;
    for (int i = 0; i < 1024; i++) {
        unsigned int w = m[i];
        if (w > 1u) allint = false;
        if (w != 0u && w != 0x3F800000u) allfloat = false;
    }
    g_mask_mode = allint ? 0 : (allfloat ? 2 : 1);
}

// ---------------------------------------------------------------------------
// Merged QKV projection (uniform single-fp16): grid z = 0(Q), 1(K), 2(V).
// BM=128, BN=128, BK=16, warp tile 32x64 (2x4), double-buffered smem.
// ---------------------------------------------------------------------------
__global__ __launch_bounds__(256)
void qkv_proj(const float* __restrict__ q, const float* __restrict__ k,
              const float* __restrict__ v,
              const float* __restrict__ Wq, const float* __restrict__ Wk,
              const float* __restrict__ Wv,
              const float* __restrict__ bq, const float* __restrict__ bk,
              const float* __restrict__ bv,
              __half* __restrict__ Qp, __half* __restrict__ Kp,
              __half* __restrict__ Vp) {
    constexpr int LDA = 24;
    constexpr int LDW = 136;
    constexpr int LDST = 132;

    __shared__ __align__(16) char buf[33792];
    __half* As = (__half*)buf;          // [2][128][24]
    __half* Ws = As + 2 * 128 * LDA;    // [2][16][136]
    float* stg = (float*)buf;           // [64][132] epilogue reuse

    const int z = blockIdx.z;
    const float* A    = (z == 0) ? q  : (z == 1) ? k  : v;
    const float* W    = (z == 0) ? Wq : (z == 1) ? Wk : Wv;
    const float* bias = (z == 0) ? bq : (z == 1) ? bk : bv;
    __half* C         = (z == 0) ? Qp : (z == 1) ? Kp : Vp;

    const int tid = threadIdx.x;
    const int w = tid >> 5;
    const int wm = w >> 1;
    const int wn = w & 1;
    const int row0 = blockIdx.y * 128;
    const int col0 = blockIdx.x * 128;

    const int ar = tid >> 2, ac = (tid & 3) * 4;
    const int wr0 = tid >> 5, wc0 = (tid & 31) * 4;

    hfrag_c acc[2][4];
#pragma unroll
    for (int ti = 0; ti < 2; ti++)
#pragma unroll
        for (int tj = 0; tj < 4; tj++) wmma::fill_fragment(acc[ti][tj], 0.0f);

    float4 ra0, ra1, rw0, rw1;
    ra0 = *(const float4*)&A[(size_t)(row0 + ar) * Dc + ac];
    ra1 = *(const float4*)&A[(size_t)(row0 + ar + 64) * Dc + ac];
    rw0 = *(const float4*)&W[(size_t)wr0 * HDc + col0 + wc0];
    rw1 = *(const float4*)&W[(size_t)(wr0 + 8) * HDc + col0 + wc0];
    cvt_store4_h(As + ar * LDA + ac, ra0);
    cvt_store4_h(As + (ar + 64) * LDA + ac, ra1);
    cvt_store4_h(Ws + wr0 * LDW + wc0, rw0);
    cvt_store4_h(Ws + (wr0 + 8) * LDW + wc0, rw1);
    __syncthreads();

    for (int kt = 0; kt < 64; kt++) {
        if (kt < 63) {
            int kk = (kt + 1) * 16;
            ra0 = *(const float4*)&A[(size_t)(row0 + ar) * Dc + kk + ac];
            ra1 = *(const float4*)&A[(size_t)(row0 + ar + 64) * Dc + kk + ac];
            rw0 = *(const float4*)&W[(size_t)(kk + wr0) * HDc + col0 + wc0];
            rw1 = *(const float4*)&W[(size_t)(kk + wr0 + 8) * HDc + col0 + wc0];
        }
        const int cur = kt & 1;
        const int cb = cur * 128 * LDA;
        const int wb = cur * 16 * LDW;

        hfrag_a fa[2];
#pragma unroll
        for (int ti = 0; ti < 2; ti++)
            wmma::load_matrix_sync(fa[ti], As + cb + (wm * 32 + ti * 16) * LDA, LDA);
#pragma unroll
        for (int tj = 0; tj < 4; tj++) {
            hfrag_b fb;
            wmma::load_matrix_sync(fb, Ws + wb + wn * 64 + tj * 16, LDW);
#pragma unroll
            for (int ti = 0; ti < 2; ti++)
                wmma::mma_sync(acc[ti][tj], fa[ti], fb, acc[ti][tj]);
        }

        if (kt < 63) {
            const int nb = (cur ^ 1) * 128 * LDA;
            const int nw = (cur ^ 1) * 16 * LDW;
            cvt_store4_h(As + nb + ar * LDA + ac, ra0);
            cvt_store4_h(As + nb + (ar + 64) * LDA + ac, ra1);
            cvt_store4_h(Ws + nw + wr0 * LDW + wc0, rw0);
            cvt_store4_h(Ws + nw + (wr0 + 8) * LDW + wc0, rw1);
        }
        __syncthreads();
    }

#pragma unroll
    for (int ph = 0; ph < 2; ph++) {
        if ((wm >> 1) == ph) {
#pragma unroll
            for (int ti = 0; ti < 2; ti++)
#pragma unroll
                for (int tj = 0; tj < 4; tj++)
                    wmma::store_matrix_sync(&stg[((wm & 1) * 32 + ti * 16) * LDST + wn * 64 + tj * 16],
                                            acc[ti][tj], LDST, wmma::mem_row_major);
        }
        __syncthreads();
#pragma unroll
        for (int i = tid; i < 2048; i += 256) {
            int r = i >> 5, c4 = (i & 31) * 4;
            int m = row0 + ph * 64 + r;
            int col = col0 + c4;
            float4 vv = *(float4*)&stg[r * LDST + c4];
            float4 bi = *(const float4*)&bias[col];
            vv.x += bi.x; vv.y += bi.y; vv.z += bi.z; vv.w += bi.w;
            int b = m >> 10, s = m & 1023, h = col >> 6, d = col & 63;
            cvt_store4_h(C + (((size_t)b * Hc + h) * Sc + s) * 64 + d, vv);
        }
        __syncthreads();
    }
}

// ---------------------------------------------------------------------------
// Scores (raw, unmasked, unscaled): 128x128 tile per block, warp tile 32x64.
// Accumulators stored DIRECTLY to gmem (ld=1024). Mask+scale in softmax.
// ---------------------------------------------------------------------------
__global__ __launch_bounds__(256)
void scores_big(const __half* __restrict__ Qp, const __half* __restrict__ Kp,
                float* __restrict__ attn) {
    constexpr int LDT = 72;
    __shared__ __align__(16) __half Qs[128 * LDT];
    __shared__ __align__(16) __half Ks[128 * LDT];

    const int z = blockIdx.z;
    const int q0 = blockIdx.y * 128;
    const int k0 = blockIdx.x * 128;
    const int tid = threadIdx.x;
    const int w = tid >> 5;
    const int wm = w & 3;
    const int wn = w >> 2;

    const size_t zb = (size_t)z * Sc * 64;

#pragma unroll
    for (int i = tid; i < 1024; i += 256) {
        int r = i >> 3, c = (i & 7) * 8;
        *(uint4*)&Qs[r * LDT + c] = *(const uint4*)&Qp[zb + (size_t)(q0 + r) * 64 + c];
        *(uint4*)&Ks[r * LDT + c] = *(const uint4*)&Kp[zb + (size_t)(k0 + r) * 64 + c];
    }
    __syncthreads();

    hfrag_c acc[2][4];
#pragma unroll
    for (int ti = 0; ti < 2; ti++)
#pragma unroll
        for (int tj = 0; tj < 4; tj++) wmma::fill_fragment(acc[ti][tj], 0.0f);

#pragma unroll
    for (int ks = 0; ks < 4; ks++) {
        const int kb = ks * 16;
        hfrag_a fa[2];
#pragma unroll
        for (int ti = 0; ti < 2; ti++)
            wmma::load_matrix_sync(fa[ti], Qs + (wm * 32 + ti * 16) * LDT + kb, LDT);
#pragma unroll
        for (int tj = 0; tj < 4; tj++) {
            hfrag_bc fb;
            wmma::load_matrix_sync(fb, Ks + (wn * 64 + tj * 16) * LDT + kb, LDT);
#pragma unroll
            for (int ti = 0; ti < 2; ti++)
                wmma::mma_sync(acc[ti][tj], fa[ti], fb, acc[ti][tj]);
        }
    }

#pragma unroll
    for (int ti = 0; ti < 2; ti++)
#pragma unroll
        for (int tj = 0; tj < 4; tj++) {
            int qq = q0 + wm * 32 + ti * 16;
            int kk = k0 + wn * 64 + tj * 16;
            wmma::store_matrix_sync(&attn[((size_t)z * Sc + qq) * Sc + kk],
                                    acc[ti][tj], Sc, wmma::mem_row_major);
        }
}

// ---------------------------------------------------------------------------
// Softmax with fused mask + scale; in place; emits fp16 probs (packed store).
// Streaming cache hints on the score read / prob write (mask stays cached).
// ---------------------------------------------------------------------------
__global__ __launch_bounds__(256)
void softmax_kernel(float* __restrict__ attn, __half* __restrict__ attn_h,
                    const void* __restrict__ mask) {
    const size_t row = blockIdx.x;       // z*Sc + q
    const int b = (int)(row >> 14);
    const int qrow = (int)(row & 1023);
    float4* p = (float4*)(attn + row * Sc);
    __half* ph = attn_h + row * Sc;
    const int tid = threadIdx.x;
    const int lane = tid & 31, wid = tid >> 5;
    __shared__ float sm[16];

    const size_t mrow = ((size_t)b * Sc + qrow) * Sc;
    const int mode = g_mask_mode;

    float4 v = __ldcs(&p[tid]);
    {
        bool m0, m1, m2, m3;
        if (mode == 0) {
            int4 mi = *(const int4*)((const int*)mask + mrow + tid * 4);
            m0 = mi.x != 0; m1 = mi.y != 0; m2 = mi.z != 0; m3 = mi.w != 0;
        } else if (mode == 2) {
            float4 mf = *(const float4*)((const float*)mask + mrow + tid * 4);
            m0 = mf.x != 0.0f; m1 = mf.y != 0.0f; m2 = mf.z != 0.0f; m3 = mf.w != 0.0f;
        } else {
            uchar4 mb = *(const uchar4*)((const unsigned char*)mask + mrow + tid * 4);
            m0 = mb.x != 0; m1 = mb.y != 0; m2 = mb.z != 0; m3 = mb.w != 0;
        }
        v.x = m0 ? -1e9f : v.x * 0.125f;
        v.y = m1 ? -1e9f : v.y * 0.125f;
        v.z = m2 ? -1e9f : v.z * 0.125f;
        v.w = m3 ? -1e9f : v.w * 0.125f;
    }

    float mx = fmaxf(fmaxf(v.x, v.y), fmaxf(v.z, v.w));
#pragma unroll
    for (int o = 16; o; o >>= 1) mx = fmaxf(mx, __shfl_xor_sync(0xffffffffu, mx, o));
    if (lane == 0) sm[wid] = mx;
    __syncthreads();
    float m = sm[0];
#pragma unroll
    for (int i = 1; i < 8; i++) m = fmaxf(m, sm[i]);

    v.x = expf(v.x - m); v.y = expf(v.y - m);
    v.z = expf(v.z - m); v.w = expf(v.w - m);
    float s = (v.x + v.y) + (v.z + v.w);
#pragma unroll
    for (int o = 16; o; o >>= 1) s += __shfl_xor_sync(0xffffffffu, s, o);
    if (lane == 0) sm[8 + wid] = s;
    __syncthreads();
    float tot = 0.0f;
#pragma unroll
    for (int i = 0; i < 8; i++) tot += sm[8 + i];
    float inv = 1.0f / tot;
    v.x *= inv; v.y *= inv; v.z *= inv; v.w *= inv;
    __stcs(&p[tid], v);
    cvt_store4_h(ph + tid * 4, v);
}

// ---------------------------------------------------------------------------
// Context: BM=256, BN=64, single fp16, warp tile 32x64 (R7-proven shape).
// ---------------------------------------------------------------------------
__global__ __launch_bounds__(256)
void context_wide(const __half* __restrict__ P, const __half* __restrict__ Vp,
                  __half* __restrict__ C) {
    constexpr int LDA = 24;
    constexpr int LDW = 72;
    constexpr int LDST = 68;

    __shared__ __align__(16) char buf[34816];
    __half* As = (__half*)buf;
    __half* Ws = As + 2 * 256 * LDA;
    float* stg = (float*)buf;

    const int tid = threadIdx.x;
    const int w = tid >> 5;
    const int z = blockIdx.y;
    const int row0 = blockIdx.x * 256;

    const __half* Pb = P + (size_t)z * Sc * Sc;
    const __half* Vb = Vp + (size_t)z * Sc * 64;

    const int ar = tid >> 1, ac = (tid & 1) * 8;
    const int in_b = tid < 128;
    const int wr = tid >> 3, wc = (tid & 7) * 8;

    hfrag_c acc[2][4];
#pragma unroll
    for (int ti = 0; ti < 2; ti++)
#pragma unroll
        for (int tj = 0; tj < 4; tj++) wmma::fill_fragment(acc[ti][tj], 0.0f);

    uint4 pa0, pa1, pb;
    pa0 = *(const uint4*)&Pb[(size_t)(row0 + ar) * Sc + ac];
    pa1 = *(const uint4*)&Pb[(size_t)(row0 + ar + 128) * Sc + ac];
    if (in_b) pb = *(const uint4*)&Vb[(size_t)wr * 64 + wc];
    *(uint4*)&As[ar * LDA + ac] = pa0;
    *(uint4*)&As[(ar + 128) * LDA + ac] = pa1;
    if (in_b) *(uint4*)&Ws[wr * LDW + wc] = pb;
    __syncthreads();

    for (int kt = 0; kt < 64; kt++) {
        if (kt < 63) {
            int kk = (kt + 1) * 16;
            pa0 = *(const uint4*)&Pb[(size_t)(row0 + ar) * Sc + kk + ac];
            pa1 = *(const uint4*)&Pb[(size_t)(row0 + ar + 128) * Sc + kk + ac];
            if (in_b) pb = *(const uint4*)&Vb[(size_t)(kk + wr) * 64 + wc];
        }
        const int cur = kt & 1;
        const int cb = cur * 256 * LDA;
        const int wb = cur * 16 * LDW;

        hfrag_a fa[2];
#pragma unroll
        for (int ti = 0; ti < 2; ti++)
            wmma::load_matrix_sync(fa[ti], As + cb + (w * 32 + ti * 16) * LDA, LDA);
#pragma unroll
        for (int tj = 0; tj < 4; tj++) {
            hfrag_b fb;
            wmma::load_matrix_sync(fb, Ws + wb + tj * 16, LDW);
#pragma unroll
            for (int ti = 0; ti < 2; ti++)
                wmma::mma_sync(acc[ti][tj], fa[ti], fb, acc[ti][tj]);
        }

        if (kt < 63) {
            const int nb = (cur ^ 1) * 256 * LDA;
            const int nw = (cur ^ 1) * 16 * LDW;
            *(uint4*)&As[nb + ar * LDA + ac] = pa0;
            *(uint4*)&As[nb + (ar + 128) * LDA + ac] = pa1;
            if (in_b) *(uint4*)&Ws[nw + wr * LDW + wc] = pb;
        }
        __syncthreads();
    }

    const int b = z >> 4, h = z & 15;
#pragma unroll
    for (int ph = 0; ph < 2; ph++) {
        if ((w >> 2) == ph) {
#pragma unroll
            for (int ti = 0; ti < 2; ti++)
#pragma unroll
                for (int tj = 0; tj < 4; tj++)
                    wmma::store_matrix_sync(&stg[((w & 3) * 32 + ti * 16) * LDST + tj * 16],
                                            acc[ti][tj], LDST, wmma::mem_row_major);
        }
        __syncthreads();
#pragma unroll
        for (int i = tid; i < 2048; i += 256) {
            int r = i >> 4, c4 = (i & 15) * 4;
            int s = row0 + ph * 128 + r;
            float4 vv = *(float4*)&stg[r * LDST + c4];
            cvt_store4_h(C + ((size_t)(b * Sc + s)) * HDc + h * DVc + c4, vv);
        }
        __syncthreads();
    }
}

// ---------------------------------------------------------------------------
// Out-proj: BM=128, BN=128, single fp16, fp32 out (R7-proven shape).
// ---------------------------------------------------------------------------
__global__ __launch_bounds__(256)
void outproj_wide(const __half* __restrict__ Ab, const float* __restrict__ W,
                  const float* __restrict__ bias, float* __restrict__ Cf) {
    constexpr int LDA = 24;
    constexpr int LDW = 136;
    constexpr int LDST = 132;

    __shared__ __align__(16) char buf[33792];
    __half* As = (__half*)buf;
    __half* Ws = As + 2 * 128 * LDA;
    float* stg = (float*)buf;

    const int tid = threadIdx.x;
    const int w = tid >> 5;
    const int wm = w >> 1;
    const int wn = w & 1;
    const int row0 = blockIdx.y * 128;
    const int col0 = blockIdx.x * 128;

    const int br = tid >> 1, bc = (tid & 1) * 8;
    const int wr0 = tid >> 5, wc0 = (tid & 31) * 4;

    hfrag_c acc[2][4];
#pragma unroll
    for (int ti = 0; ti < 2; ti++)
#pragma unroll
        for (int tj = 0; tj < 4; tj++) wmma::fill_fragment(acc[ti][tj], 0.0f);

    uint4 pa;
    float4 rw0, rw1;
    pa = *(const uint4*)&Ab[(size_t)(row0 + br) * Dc + bc];
    rw0 = *(const float4*)&W[(size_t)wr0 * Dc + col0 + wc0];
    rw1 = *(const float4*)&W[(size_t)(wr0 + 8) * Dc + col0 + wc0];
    *(uint4*)&As[br * LDA + bc] = pa;
    cvt_store4_h(Ws + wr0 * LDW + wc0, rw0);
    cvt_store4_h(Ws + (wr0 + 8) * LDW + wc0, rw1);
    __syncthreads();

    for (int kt = 0; kt < 64; kt++) {
        if (kt < 63) {
            int kk = (kt + 1) * 16;
            pa = *(const uint4*)&Ab[(size_t)(row0 + br) * Dc + kk + bc];
            rw0 = *(const float4*)&W[(size_t)(kk + wr0) * Dc + col0 + wc0];
            rw1 = *(const float4*)&W[(size_t)(kk + wr0 + 8) * Dc + col0 + wc0];
        }
        const int cur = kt & 1;
        const int cb = cur * 128 * LDA;
        const int wb = cur * 16 * LDW;

        hfrag_a fa[2];
#pragma unroll
        for (int ti = 0; ti < 2; ti++)
            wmma::load_matrix_sync(fa[ti], As + cb + (wm * 32 + ti * 16) * LDA, LDA);
#pragma unroll
        for (int tj = 0; tj < 4; tj++) {
            hfrag_b fb;
            wmma::load_matrix_sync(fb, Ws + wb + wn * 64 + tj * 16, LDW);
#pragma unroll
            for (int ti = 0; ti < 2; ti++)
                wmma::mma_sync(acc[ti][tj], fa[ti], fb, acc[ti][tj]);
        }

        if (kt < 63) {
            const int nb = (cur ^ 1) * 128 * LDA;
            const int nw = (cur ^ 1) * 16 * LDW;
            *(uint4*)&As[nb + br * LDA + bc] = pa;
            cvt_store4_h(Ws + nw + wr0 * LDW + wc0, rw0);
            cvt_store4_h(Ws + nw + (wr0 + 8) * LDW + wc0, rw1);
        }
        __syncthreads();
    }

#pragma unroll
    for (int ph = 0; ph < 2; ph++) {
        if ((wm >> 1) == ph) {
#pragma unroll
            for (int ti = 0; ti < 2; ti++)
#pragma unroll
                for (int tj = 0; tj < 4; tj++)
                    wmma::store_matrix_sync(&stg[((wm & 1) * 32 + ti * 16) * LDST + wn * 64 + tj * 16],
                                            acc[ti][tj], LDST, wmma::mem_row_major);
        }
        __syncthreads();
#pragma unroll
        for (int i = tid; i < 2048; i += 256) {
            int r = i >> 5, c4 = (i & 31) * 4;
            int m = row0 + ph * 64 + r;
            int col = col0 + c4;
            float4 vv = *(float4*)&stg[r * LDST + c4];
            float4 bi = *(const float4*)&bias[col];
            vv.x += bi.x; vv.y += bi.y; vv.z += bi.z; vv.w += bi.w;
            *(float4*)&Cf[(size_t)m * Dc + col] = vv;
        }
        __syncthreads();
    }
}

// ---------------------------------------------------------------------------
// Fused residual add + LayerNorm
// ---------------------------------------------------------------------------
__global__ __launch_bounds__(256)
void layernorm_kernel(const float* __restrict__ x, const float* __restrict__ resid,
                      float* __restrict__ out) {
    const size_t row = blockIdx.x;
    const float4* xr = (const float4*)(x + row * Dc);
    const float4* rr = (const float4*)(resid + row * Dc);
    float4* orow = (float4*)(out + row * Dc);
    const int tid = threadIdx.x;
    const int lane = tid & 31, wid = tid >> 5;
    __shared__ float sm[16];

    float4 a = xr[tid], b = rr[tid];
    float4 v = make_float4(a.x + b.x, a.y + b.y, a.z + b.z, a.w + b.w);
    float s = (v.x + v.y) + (v.z + v.w);
#pragma unroll
    for (int o = 16; o; o >>= 1) s += __shfl_xor_sync(0xffffffffu, s, o);
    if (lane == 0) sm[wid] = s;
    __syncthreads();
    float tot = 0.0f;
#pragma unroll
    for (int i = 0; i < 8; i++) tot += sm[i];
    float mean = tot * (1.0f / 1024.0f);

    float dx = v.x - mean, dy = v.y - mean, dz = v.z - mean, dw = v.w - mean;
    float vs = (dx * dx + dy * dy) + (dz * dz + dw * dw);
#pragma unroll
    for (int o = 16; o; o >>= 1) vs += __shfl_xor_sync(0xffffffffu, vs, o);
    if (lane == 0) sm[8 + wid] = vs;
    __syncthreads();
    float vtot = 0.0f;
#pragma unroll
    for (int i = 0; i < 8; i++) vtot += sm[8 + i];
    float inv = rsqrtf(vtot * (1.0f / 1024.0f) + 1e-5f);
    orow[tid] = make_float4(dx * inv, dy * inv, dz * inv, dw * inv);
}

// ---------------------------------------------------------------------------
// Launch
// ---------------------------------------------------------------------------
extern "C" void kernel_launch(void* const* d_in, const int* in_sizes, int n_in,
                              void* d_out, int out_size) {
    const float* q    = (const float*)d_in[0];
    const float* k    = (const float*)d_in[1];
    const float* v    = (const float*)d_in[2];
    const void*  mask = d_in[3];
    const float* Wq   = (const float*)d_in[4];
    const float* bq   = (const float*)d_in[5];
    const float* Wk   = (const float*)d_in[6];
    const float* bk   = (const float*)d_in[7];
    const float* Wv   = (const float*)d_in[8];
    const float* bv   = (const float*)d_in[9];
    const float* Wo   = (const float*)d_in[10];
    const float* bo   = (const float*)d_in[11];
    float* out = (float*)d_out;

    __half *Qp, *Kp, *Vp, *ctx, *attn_h;
    float *obuf, *attn_fb;
    cudaGetSymbolAddress((void**)&Qp, g_Qp);
    cudaGetSymbolAddress((void**)&Kp, g_Kp);
    cudaGetSymbolAddress((void**)&Vp, g_Vp);
    cudaGetSymbolAddress((void**)&ctx, g_ctx);
    cudaGetSymbolAddress((void**)&attn_h, g_attn_h);
    cudaGetSymbolAddress((void**)&obuf, g_obuf);
    cudaGetSymbolAddress((void**)&attn_fb, g_attn_fb);

    const long long LN_ELEMS = (long long)Mc * Dc;
    const long long ATTN_ELEMS = (long long)Bc * Hc * Sc * Sc;
    float* attn = ((long long)out_size >= LN_ELEMS + ATTN_ELEMS)
                      ? (out + (size_t)LN_ELEMS)
                      : attn_fb;

    detect_mask_kernel<<<1, 1>>>((const unsigned int*)mask);

    // Merged QKV projections, single fp16 (z: 0=Q, 1=K, 2=V)
    qkv_proj<<<dim3(8, 32, 3), 256>>>(q, k, v, Wq, Wk, Wv, bq, bk, bv, Qp, Kp, Vp);

    // Raw scores (128x128 tiles, direct gmem store)
    scores_big<<<dim3(8, 8, Bc * Hc), 256>>>(Qp, Kp, attn);

    // Softmax with fused mask+scale, in place; emits fp16 probs
    softmax_kernel<<<Bc * Hc * Sc, 256>>>(attn, attn_h, mask);

    // Context (fp16 probs @ fp16 V) -> fp16 ctx plane
    context_wide<<<dim3(4, 64), 256>>>(attn_h, Vp, ctx);

    // Output projection (fp16 A, fp32 out)
    outproj_wide<<<dim3(8, 32), 256>>>(ctx, Wo, bo, obuf);

    // Residual + LayerNorm
    layernorm_kernel<<<Mc, 256>>>(obuf, q, out);
}

// round 17
// speedup vs baseline: 1.1711x; 1.0316x over previous
#include <cuda_runtime.h>
#include <cuda_fp16.h>
#include <mma.h>
#include <cstddef>

using namespace nvcuda;

#define Bc 4
#define Sc 1024
#define Dc 1024
#define Hc 16
#define DKc 64
#define DVc 64
#define Mc (Bc * Sc)
#define HDc (Hc * DKc)
#define QP_ELEMS (Mc * HDc)

// ---------------- Static device scratch (fp16) ----------------
__device__ __half g_Qp[QP_ELEMS];                    // [B,H,S,64]
__device__ __half g_Kp[QP_ELEMS];
__device__ __half g_Vp[QP_ELEMS];
__device__ __half g_ctx[Mc * HDc];                   // [B,S,1024]
__device__ __half g_attn_h[(size_t)Bc * Hc * Sc * Sc];  // fp16 probs
__device__ __half g_score_h[(size_t)Bc * Hc * Sc * Sc]; // fp16 raw scores
__device__ float g_obuf[Mc * Dc];
__device__ float g_attn_fb[(size_t)Bc * Hc * Sc * Sc];
__device__ int   g_mask_mode;

using hfrag_a  = wmma::fragment<wmma::matrix_a, 16, 16, 16, __half, wmma::row_major>;
using hfrag_b  = wmma::fragment<wmma::matrix_b, 16, 16, 16, __half, wmma::row_major>;
using hfrag_bc = wmma::fragment<wmma::matrix_b, 16, 16, 16, __half, wmma::col_major>;
using hfrag_c  = wmma::fragment<wmma::accumulator, 16, 16, 16, float>;

// Packed fp32x4 -> fp16x4 store: 2x cvt.rn.f16x2.f32 + ONE 8-byte store.
__device__ __forceinline__ void cvt_store4_h(__half* d, float4 v) {
    union { __half2 h2[2]; uint2 u; } pk;
    pk.h2[0] = __floats2half2_rn(v.x, v.y);
    pk.h2[1] = __floats2half2_rn(v.z, v.w);
    *(uint2*)d = pk.u;
}

__device__ __forceinline__ float4 load4_h(const __half* s) {
    union { __half2 h2[2]; uint2 u; } pk;
    pk.u = *(const uint2*)s;
    float2 a = __half22float2(pk.h2[0]);
    float2 b = __half22float2(pk.h2[1]);
    return make_float4(a.x, a.y, b.x, b.y);
}

// ---------------------------------------------------------------------------
__global__ void detect_mask_kernel(const unsigned int* __restrict__ m) {
    bool allint = true, allfloat = true;
    for (int i = 0; i < 1024; i++) {
        unsigned int w = m[i];
        if (w > 1u) allint = false;
        if (w != 0u && w != 0x3F800000u) allfloat = false;
    }
    g_mask_mode = allint ? 0 : (allfloat ? 2 : 1);
}

// ---------------------------------------------------------------------------
// Merged QKV projection (uniform single-fp16): grid z = 0(Q), 1(K), 2(V).
// BM=128, BN=128, BK=16, warp tile 32x64 (2x4), double-buffered smem.
// ---------------------------------------------------------------------------
__global__ __launch_bounds__(256)
void qkv_proj(const float* __restrict__ q, const float* __restrict__ k,
              const float* __restrict__ v,
              const float* __restrict__ Wq, const float* __restrict__ Wk,
              const float* __restrict__ Wv,
              const float* __restrict__ bq, const float* __restrict__ bk,
              const float* __restrict__ bv,
              __half* __restrict__ Qp, __half* __restrict__ Kp,
              __half* __restrict__ Vp) {
    constexpr int LDA = 24;
    constexpr int LDW = 136;
    constexpr int LDST = 132;

    __shared__ __align__(16) char buf[33792];
    __half* As = (__half*)buf;          // [2][128][24]
    __half* Ws = As + 2 * 128 * LDA;    // [2][16][136]
    float* stg = (float*)buf;           // [64][132] epilogue reuse

    const int z = blockIdx.z;
    const float* A    = (z == 0) ? q  : (z == 1) ? k  : v;
    const float* W    = (z == 0) ? Wq : (z == 1) ? Wk : Wv;
    const float* bias = (z == 0) ? bq : (z == 1) ? bk : bv;
    __half* C         = (z == 0) ? Qp : (z == 1) ? Kp : Vp;

    const int tid = threadIdx.x;
    const int w = tid >> 5;
    const int wm = w >> 1;
    const int wn = w & 1;
    const int row0 = blockIdx.y * 128;
    const int col0 = blockIdx.x * 128;

    const int ar = tid >> 2, ac = (tid & 3) * 4;
    const int wr0 = tid >> 5, wc0 = (tid & 31) * 4;

    hfrag_c acc[2][4];
#pragma unroll
    for (int ti = 0; ti < 2; ti++)
#pragma unroll
        for (int tj = 0; tj < 4; tj++) wmma::fill_fragment(acc[ti][tj], 0.0f);

    float4 ra0, ra1, rw0, rw1;
    ra0 = *(const float4*)&A[(size_t)(row0 + ar) * Dc + ac];
    ra1 = *(const float4*)&A[(size_t)(row0 + ar + 64) * Dc + ac];
    rw0 = *(const float4*)&W[(size_t)wr0 * HDc + col0 + wc0];
    rw1 = *(const float4*)&W[(size_t)(wr0 + 8) * HDc + col0 + wc0];
    cvt_store4_h(As + ar * LDA + ac, ra0);
    cvt_store4_h(As + (ar + 64) * LDA + ac, ra1);
    cvt_store4_h(Ws + wr0 * LDW + wc0, rw0);
    cvt_store4_h(Ws + (wr0 + 8) * LDW + wc0, rw1);
    __syncthreads();

    for (int kt = 0; kt < 64; kt++) {
        if (kt < 63) {
            int kk = (kt + 1) * 16;
            ra0 = *(const float4*)&A[(size_t)(row0 + ar) * Dc + kk + ac];
            ra1 = *(const float4*)&A[(size_t)(row0 + ar + 64) * Dc + kk + ac];
            rw0 = *(const float4*)&W[(size_t)(kk + wr0) * HDc + col0 + wc0];
            rw1 = *(const float4*)&W[(size_t)(kk + wr0 + 8) * HDc + col0 + wc0];
        }
        const int cur = kt & 1;
        const int cb = cur * 128 * LDA;
        const int wb = cur * 16 * LDW;

        hfrag_a fa[2];
#pragma unroll
        for (int ti = 0; ti < 2; ti++)
            wmma::load_matrix_sync(fa[ti], As + cb + (wm * 32 + ti * 16) * LDA, LDA);
#pragma unroll
        for (int tj = 0; tj < 4; tj++) {
            hfrag_b fb;
            wmma::load_matrix_sync(fb, Ws + wb + wn * 64 + tj * 16, LDW);
#pragma unroll
            for (int ti = 0; ti < 2; ti++)
                wmma::mma_sync(acc[ti][tj], fa[ti], fb, acc[ti][tj]);
        }

        if (kt < 63) {
            const int nb = (cur ^ 1) * 128 * LDA;
            const int nw = (cur ^ 1) * 16 * LDW;
            cvt_store4_h(As + nb + ar * LDA + ac, ra0);
            cvt_store4_h(As + nb + (ar + 64) * LDA + ac, ra1);
            cvt_store4_h(Ws + nw + wr0 * LDW + wc0, rw0);
            cvt_store4_h(Ws + nw + (wr0 + 8) * LDW + wc0, rw1);
        }
        __syncthreads();
    }

#pragma unroll
    for (int ph = 0; ph < 2; ph++) {
        if ((wm >> 1) == ph) {
#pragma unroll
            for (int ti = 0; ti < 2; ti++)
#pragma unroll
                for (int tj = 0; tj < 4; tj++)
                    wmma::store_matrix_sync(&stg[((wm & 1) * 32 + ti * 16) * LDST + wn * 64 + tj * 16],
                                            acc[ti][tj], LDST, wmma::mem_row_major);
        }
        __syncthreads();
#pragma unroll
        for (int i = tid; i < 2048; i += 256) {
            int r = i >> 5, c4 = (i & 31) * 4;
            int m = row0 + ph * 64 + r;
            int col = col0 + c4;
            float4 vv = *(float4*)&stg[r * LDST + c4];
            float4 bi = *(const float4*)&bias[col];
            vv.x += bi.x; vv.y += bi.y; vv.z += bi.z; vv.w += bi.w;
            int b = m >> 10, s = m & 1023, h = col >> 6, d = col & 63;
            cvt_store4_h(C + (((size_t)b * Hc + h) * Sc + s) * 64 + d, vv);
        }
        __syncthreads();
    }
}

// ---------------------------------------------------------------------------
// Scores (raw, unmasked, unscaled) -> fp16 gmem. 128x128 tile per block,
// warp tile 32x64. Two-phase smem staging for the half conversion.
// Mask+scale applied by softmax.
// ---------------------------------------------------------------------------
__global__ __launch_bounds__(256)
void scores_big(const __half* __restrict__ Qp, const __half* __restrict__ Kp,
                __half* __restrict__ score_h) {
    constexpr int LDT = 72;
    constexpr int LDSG = 132;

    // union: mainloop tiles (36.9KB) vs epilogue staging (33.8KB)
    __shared__ __align__(16) char buf[36864];
    __half* Qs = (__half*)buf;              // [128][72]
    __half* Ks = Qs + 128 * LDT;            // [128][72]
    float* stg = (float*)buf;               // [64][132]

    const int z = blockIdx.z;
    const int q0 = blockIdx.y * 128;
    const int k0 = blockIdx.x * 128;
    const int tid = threadIdx.x;
    const int w = tid >> 5;
    const int wm = w & 3;
    const int wn = w >> 2;

    const size_t zb = (size_t)z * Sc * 64;

#pragma unroll
    for (int i = tid; i < 1024; i += 256) {
        int r = i >> 3, c = (i & 7) * 8;
        *(uint4*)&Qs[r * LDT + c] = *(const uint4*)&Qp[zb + (size_t)(q0 + r) * 64 + c];
        *(uint4*)&Ks[r * LDT + c] = *(const uint4*)&Kp[zb + (size_t)(k0 + r) * 64 + c];
    }
    __syncthreads();

    hfrag_c acc[2][4];
#pragma unroll
    for (int ti = 0; ti < 2; ti++)
#pragma unroll
        for (int tj = 0; tj < 4; tj++) wmma::fill_fragment(acc[ti][tj], 0.0f);

#pragma unroll
    for (int ks = 0; ks < 4; ks++) {
        const int kb = ks * 16;
        hfrag_a fa[2];
#pragma unroll
        for (int ti = 0; ti < 2; ti++)
            wmma::load_matrix_sync(fa[ti], Qs + (wm * 32 + ti * 16) * LDT + kb, LDT);
#pragma unroll
        for (int tj = 0; tj < 4; tj++) {
            hfrag_bc fb;
            wmma::load_matrix_sync(fb, Ks + (wn * 64 + tj * 16) * LDT + kb, LDT);
#pragma unroll
            for (int ti = 0; ti < 2; ti++)
                wmma::mma_sync(acc[ti][tj], fa[ti], fb, acc[ti][tj]);
        }
    }
    __syncthreads();   // tiles fully consumed; smem becomes staging

    // two-phase epilogue: rows [0,64), then [64,128); write fp16 scores
#pragma unroll
    for (int ph = 0; ph < 2; ph++) {
        if ((wm >> 1) == ph) {
#pragma unroll
            for (int ti = 0; ti < 2; ti++)
#pragma unroll
                for (int tj = 0; tj < 4; tj++)
                    wmma::store_matrix_sync(&stg[((wm & 1) * 32 + ti * 16) * LDSG + wn * 64 + tj * 16],
                                            acc[ti][tj], LDSG, wmma::mem_row_major);
        }
        __syncthreads();
#pragma unroll
        for (int i = tid; i < 2048; i += 256) {
            int r = i >> 5, c4 = (i & 31) * 4;
            int qq = q0 + ph * 64 + r;
            float4 vv = *(float4*)&stg[r * LDSG + c4];
            cvt_store4_h(score_h + ((size_t)z * Sc + qq) * Sc + k0 + c4, vv);
        }
        __syncthreads();
    }
}

// ---------------------------------------------------------------------------
// Softmax: reads fp16 scores, fused mask + scale, writes fp32 probs (output)
// + fp16 probs (for context).
// ---------------------------------------------------------------------------
__global__ __launch_bounds__(256)
void softmax_kernel(const __half* __restrict__ score_h, float* __restrict__ attn,
                    __half* __restrict__ attn_h, const void* __restrict__ mask) {
    const size_t row = blockIdx.x;       // z*Sc + q
    const int b = (int)(row >> 14);
    const int qrow = (int)(row & 1023);
    const __half* ps = score_h + row * Sc;
    float4* p = (float4*)(attn + row * Sc);
    __half* ph = attn_h + row * Sc;
    const int tid = threadIdx.x;
    const int lane = tid & 31, wid = tid >> 5;
    __shared__ float sm[16];

    const size_t mrow = ((size_t)b * Sc + qrow) * Sc;
    const int mode = g_mask_mode;

    float4 v = load4_h(ps + tid * 4);
    {
        bool m0, m1, m2, m3;
        if (mode == 0) {
            int4 mi = *(const int4*)((const int*)mask + mrow + tid * 4);
            m0 = mi.x != 0; m1 = mi.y != 0; m2 = mi.z != 0; m3 = mi.w != 0;
        } else if (mode == 2) {
            float4 mf = *(const float4*)((const float*)mask + mrow + tid * 4);
            m0 = mf.x != 0.0f; m1 = mf.y != 0.0f; m2 = mf.z != 0.0f; m3 = mf.w != 0.0f;
        } else {
            uchar4 mb = *(const uchar4*)((const unsigned char*)mask + mrow + tid * 4);
            m0 = mb.x != 0; m1 = mb.y != 0; m2 = mb.z != 0; m3 = mb.w != 0;
        }
        v.x = m0 ? -1e9f : v.x * 0.125f;
        v.y = m1 ? -1e9f : v.y * 0.125f;
        v.z = m2 ? -1e9f : v.z * 0.125f;
        v.w = m3 ? -1e9f : v.w * 0.125f;
    }

    float mx = fmaxf(fmaxf(v.x, v.y), fmaxf(v.z, v.w));
#pragma unroll
    for (int o = 16; o; o >>= 1) mx = fmaxf(mx, __shfl_xor_sync(0xffffffffu, mx, o));
    if (lane == 0) sm[wid] = mx;
    __syncthreads();
    float m = sm[0];
#pragma unroll
    for (int i = 1; i < 8; i++) m = fmaxf(m, sm[i]);

    v.x = expf(v.x - m); v.y = expf(v.y - m);
    v.z = expf(v.z - m); v.w = expf(v.w - m);
    float s = (v.x + v.y) + (v.z + v.w);
#pragma unroll
    for (int o = 16; o; o >>= 1) s += __shfl_xor_sync(0xffffffffu, s, o);
    if (lane == 0) sm[8 + wid] = s;
    __syncthreads();
    float tot = 0.0f;
#pragma unroll
    for (int i = 0; i < 8; i++) tot += sm[8 + i];
    float inv = 1.0f / tot;
    v.x *= inv; v.y *= inv; v.z *= inv; v.w *= inv;
    __stcs(&p[tid], v);
    cvt_store4_h(ph + tid * 4, v);
}

// ---------------------------------------------------------------------------
// Context: BM=256, BN=64, single fp16, warp tile 32x64 (R7-proven shape).
// ---------------------------------------------------------------------------
__global__ __launch_bounds__(256)
void context_wide(const __half* __restrict__ P, const __half* __restrict__ Vp,
                  __half* __restrict__ C) {
    constexpr int LDA = 24;
    constexpr int LDW = 72;
    constexpr int LDST = 68;

    __shared__ __align__(16) char buf[34816];
    __half* As = (__half*)buf;
    __half* Ws = As + 2 * 256 * LDA;
    float* stg = (float*)buf;

    const int tid = threadIdx.x;
    const int w = tid >> 5;
    const int z = blockIdx.y;
    const int row0 = blockIdx.x * 256;

    const __half* Pb = P + (size_t)z * Sc * Sc;
    const __half* Vb = Vp + (size_t)z * Sc * 64;

    const int ar = tid >> 1, ac = (tid & 1) * 8;
    const int in_b = tid < 128;
    const int wr = tid >> 3, wc = (tid & 7) * 8;

    hfrag_c acc[2][4];
#pragma unroll
    for (int ti = 0; ti < 2; ti++)
#pragma unroll
        for (int tj = 0; tj < 4; tj++) wmma::fill_fragment(acc[ti][tj], 0.0f);

    uint4 pa0, pa1, pb;
    pa0 = *(const uint4*)&Pb[(size_t)(row0 + ar) * Sc + ac];
    pa1 = *(const uint4*)&Pb[(size_t)(row0 + ar + 128) * Sc + ac];
    if (in_b) pb = *(const uint4*)&Vb[(size_t)wr * 64 + wc];
    *(uint4*)&As[ar * LDA + ac] = pa0;
    *(uint4*)&As[(ar + 128) * LDA + ac] = pa1;
    if (in_b) *(uint4*)&Ws[wr * LDW + wc] = pb;
    __syncthreads();

    for (int kt = 0; kt < 64; kt++) {
        if (kt < 63) {
            int kk = (kt + 1) * 16;
            pa0 = *(const uint4*)&Pb[(size_t)(row0 + ar) * Sc + kk + ac];
            pa1 = *(const uint4*)&Pb[(size_t)(row0 + ar + 128) * Sc + kk + ac];
            if (in_b) pb = *(const uint4*)&Vb[(size_t)(kk + wr) * 64 + wc];
        }
        const int cur = kt & 1;
        const int cb = cur * 256 * LDA;
        const int wb = cur * 16 * LDW;

        hfrag_a fa[2];
#pragma unroll
        for (int ti = 0; ti < 2; ti++)
            wmma::load_matrix_sync(fa[ti], As + cb + (w * 32 + ti * 16) * LDA, LDA);
#pragma unroll
        for (int tj = 0; tj < 4; tj++) {
            hfrag_b fb;
            wmma::load_matrix_sync(fb, Ws + wb + tj * 16, LDW);
#pragma unroll
            for (int ti = 0; ti < 2; ti++)
                wmma::mma_sync(acc[ti][tj], fa[ti], fb, acc[ti][tj]);
        }

        if (kt < 63) {
            const int nb = (cur ^ 1) * 256 * LDA;
            const int nw = (cur ^ 1) * 16 * LDW;
            *(uint4*)&As[nb + ar * LDA + ac] = pa0;
            *(uint4*)&As[nb + (ar + 128) * LDA + ac] = pa1;
            if (in_b) *(uint4*)&Ws[nw + wr * LDW + wc] = pb;
        }
        __syncthreads();
    }

    const int b = z >> 4, h = z & 15;
#pragma unroll
    for (int ph = 0; ph < 2; ph++) {
        if ((w >> 2) == ph) {
#pragma unroll
            for (int ti = 0; ti < 2; ti++)
#pragma unroll
                for (int tj = 0; tj < 4; tj++)
                    wmma::store_matrix_sync(&stg[((w & 3) * 32 + ti * 16) * LDST + tj * 16],
                                            acc[ti][tj], LDST, wmma::mem_row_major);
        }
        __syncthreads();
#pragma unroll
        for (int i = tid; i < 2048; i += 256) {
            int r = i >> 4, c4 = (i & 15) * 4;
            int s = row0 + ph * 128 + r;
            float4 vv = *(float4*)&stg[r * LDST + c4];
            cvt_store4_h(C + ((size_t)(b * Sc + s)) * HDc + h * DVc + c4, vv);
        }
        __syncthreads();
    }
}

// ---------------------------------------------------------------------------
// Out-proj: BM=128, BN=128, single fp16, fp32 out (R7-proven shape).
// ---------------------------------------------------------------------------
__global__ __launch_bounds__(256)
void outproj_wide(const __half* __restrict__ Ab, const float* __restrict__ W,
                  const float* __restrict__ bias, float* __restrict__ Cf) {
    constexpr int LDA = 24;
    constexpr int LDW = 136;
    constexpr int LDST = 132;

    __shared__ __align__(16) char buf[33792];
    __half* As = (__half*)buf;
    __half* Ws = As + 2 * 128 * LDA;
    float* stg = (float*)buf;

    const int tid = threadIdx.x;
    const int w = tid >> 5;
    const int wm = w >> 1;
    const int wn = w & 1;
    const int row0 = blockIdx.y * 128;
    const int col0 = blockIdx.x * 128;

    const int br = tid >> 1, bc = (tid & 1) * 8;
    const int wr0 = tid >> 5, wc0 = (tid & 31) * 4;

    hfrag_c acc[2][4];
#pragma unroll
    for (int ti = 0; ti < 2; ti++)
#pragma unroll
        for (int tj = 0; tj < 4; tj++) wmma::fill_fragment(acc[ti][tj], 0.0f);

    uint4 pa;
    float4 rw0, rw1;
    pa = *(const uint4*)&Ab[(size_t)(row0 + br) * Dc + bc];
    rw0 = *(const float4*)&W[(size_t)wr0 * Dc + col0 + wc0];
    rw1 = *(const float4*)&W[(size_t)(wr0 + 8) * Dc + col0 + wc0];
    *(uint4*)&As[br * LDA + bc] = pa;
    cvt_store4_h(Ws + wr0 * LDW + wc0, rw0);
    cvt_store4_h(Ws + (wr0 + 8) * LDW + wc0, rw1);
    __syncthreads();

    for (int kt = 0; kt < 64; kt++) {
        if (kt < 63) {
            int kk = (kt + 1) * 16;
            pa = *(const uint4*)&Ab[(size_t)(row0 + br) * Dc + kk + bc];
            rw0 = *(const float4*)&W[(size_t)(kk + wr0) * Dc + col0 + wc0];
            rw1 = *(const float4*)&W[(size_t)(kk + wr0 + 8) * Dc + col0 + wc0];
        }
        const int cur = kt & 1;
        const int cb = cur * 128 * LDA;
        const int wb = cur * 16 * LDW;

        hfrag_a fa[2];
#pragma unroll
        for (int ti = 0; ti < 2; ti++)
            wmma::load_matrix_sync(fa[ti], As + cb + (wm * 32 + ti * 16) * LDA, LDA);
#pragma unroll
        for (int tj = 0; tj < 4; tj++) {
            hfrag_b fb;
            wmma::load_matrix_sync(fb, Ws + wb + wn * 64 + tj * 16, LDW);
#pragma unroll
            for (int ti = 0; ti < 2; ti++)
                wmma::mma_sync(acc[ti][tj], fa[ti], fb, acc[ti][tj]);
        }

        if (kt < 63) {
            const int nb = (cur ^ 1) * 128 * LDA;
            const int nw = (cur ^ 1) * 16 * LDW;
            *(uint4*)&As[nb + br * LDA + bc] = pa;
            cvt_store4_h(Ws + nw + wr0 * LDW + wc0, rw0);
            cvt_store4_h(Ws + nw + (wr0 + 8) * LDW + wc0, rw1);
        }
        __syncthreads();
    }

#pragma unroll
    for (int ph = 0; ph < 2; ph++) {
        if ((wm >> 1) == ph) {
#pragma unroll
            for (int ti = 0; ti < 2; ti++)
#pragma unroll
                for (int tj = 0; tj < 4; tj++)
                    wmma::store_matrix_sync(&stg[((wm & 1) * 32 + ti * 16) * LDST + wn * 64 + tj * 16],
                                            acc[ti][tj], LDST, wmma::mem_row_major);
        }
        __syncthreads();
#pragma unroll
        for (int i = tid; i < 2048; i += 256) {
            int r = i >> 5, c4 = (i & 31) * 4;
            int m = row0 + ph * 64 + r;
            int col = col0 + c4;
            float4 vv = *(float4*)&stg[r * LDST + c4];
            float4 bi = *(const float4*)&bias[col];
            vv.x += bi.x; vv.y += bi.y; vv.z += bi.z; vv.w += bi.w;
            *(float4*)&Cf[(size_t)m * Dc + col] = vv;
        }
        __syncthreads();
    }
}

// ---------------------------------------------------------------------------
// Fused residual add + LayerNorm
// ---------------------------------------------------------------------------
__global__ __launch_bounds__(256)
void layernorm_kernel(const float* __restrict__ x, const float* __restrict__ resid,
                      float* __restrict__ out) {
    const size_t row = blockIdx.x;
    const float4* xr = (const float4*)(x + row * Dc);
    const float4* rr = (const float4*)(resid + row * Dc);
    float4* orow = (float4*)(out + row * Dc);
    const int tid = threadIdx.x;
    const int lane = tid & 31, wid = tid >> 5;
    __shared__ float sm[16];

    float4 a = xr[tid], b = rr[tid];
    float4 v = make_float4(a.x + b.x, a.y + b.y, a.z + b.z, a.w + b.w);
    float s = (v.x + v.y) + (v.z + v.w);
#pragma unroll
    for (int o = 16; o; o >>= 1) s += __shfl_xor_sync(0xffffffffu, s, o);
    if (lane == 0) sm[wid] = s;
    __syncthreads();
    float tot = 0.0f;
#pragma unroll
    for (int i = 0; i < 8; i++) tot += sm[i];
    float mean = tot * (1.0f / 1024.0f);

    float dx = v.x - mean, dy = v.y - mean, dz = v.z - mean, dw = v.w - mean;
    float vs = (dx * dx + dy * dy) + (dz * dz + dw * dw);
#pragma unroll
    for (int o = 16; o; o >>= 1) vs += __shfl_xor_sync(0xffffffffu, vs, o);
    if (lane == 0) sm[8 + wid] = vs;
    __syncthreads();
    float vtot = 0.0f;
#pragma unroll
    for (int i = 0; i < 8; i++) vtot += sm[8 + i];
    float inv = rsqrtf(vtot * (1.0f / 1024.0f) + 1e-5f);
    orow[tid] = make_float4(dx * inv, dy * inv, dz * inv, dw * inv);
}

// ---------------------------------------------------------------------------
// Launch
// ---------------------------------------------------------------------------
extern "C" void kernel_launch(void* const* d_in, const int* in_sizes, int n_in,
                              void* d_out, int out_size) {
    const float* q    = (const float*)d_in[0];
    const float* k    = (const float*)d_in[1];
    const float* v    = (const float*)d_in[2];
    const void*  mask = d_in[3];
    const float* Wq   = (const float*)d_in[4];
    const float* bq   = (const float*)d_in[5];
    const float* Wk   = (const float*)d_in[6];
    const float* bk   = (const float*)d_in[7];
    const float* Wv   = (const float*)d_in[8];
    const float* bv   = (const float*)d_in[9];
    const float* Wo   = (const float*)d_in[10];
    const float* bo   = (const float*)d_in[11];
    float* out = (float*)d_out;

    __half *Qp, *Kp, *Vp, *ctx, *attn_h, *score_h;
    float *obuf, *attn_fb;
    cudaGetSymbolAddress((void**)&Qp, g_Qp);
    cudaGetSymbolAddress((void**)&Kp, g_Kp);
    cudaGetSymbolAddress((void**)&Vp, g_Vp);
    cudaGetSymbolAddress((void**)&ctx, g_ctx);
    cudaGetSymbolAddress((void**)&attn_h, g_attn_h);
    cudaGetSymbolAddress((void**)&score_h, g_score_h);
    cudaGetSymbolAddress((void**)&obuf, g_obuf);
    cudaGetSymbolAddress((void**)&attn_fb, g_attn_fb);

    const long long LN_ELEMS = (long long)Mc * Dc;
    const long long ATTN_ELEMS = (long long)Bc * Hc * Sc * Sc;
    float* attn = ((long long)out_size >= LN_ELEMS + ATTN_ELEMS)
                      ? (out + (size_t)LN_ELEMS)
                      : attn_fb;

    detect_mask_kernel<<<1, 1>>>((const unsigned int*)mask);

    // Merged QKV projections, single fp16 (z: 0=Q, 1=K, 2=V)
    qkv_proj<<<dim3(8, 32, 3), 256>>>(q, k, v, Wq, Wk, Wv, bq, bk, bv, Qp, Kp, Vp);

    // Raw scores -> fp16 (128x128 tiles, staged epilogue)
    scores_big<<<dim3(8, 8, Bc * Hc), 256>>>(Qp, Kp, score_h);

    // Softmax: fp16 scores in, mask+scale fused; fp32 probs out + fp16 probs
    softmax_kernel<<<Bc * Hc * Sc, 256>>>(score_h, attn, attn_h, mask);

    // Context (fp16 probs @ fp16 V) -> fp16 ctx plane
    context_wide<<<dim3(4, 64), 256>>>(attn_h, Vp, ctx);

    // Output projection (fp16 A, fp32 out)
    outproj_wide<<<dim3(8, 32), 256>>>(ctx, Wo, bo, obuf);

    // Residual + LayerNorm
    layernorm_kernel<<<Mc, 256>>>(obuf, q, out);
}